// round 2
// baseline (speedup 1.0000x reference)
#include <cuda_runtime.h>
#include <cuda_bf16.h>
#include <cstdint>
#include <cstddef>

#define H    1024
#define FF   2048
#define G3   3072
#define SEQ  64      // batch dim of x, acts as GRU sequence length
#define T    30
#define NSEG 8
#define SUB  4
#define R    240     // T * NSEG independent GRU runs
#define DT   (1.0f/32.0f)

// ---------------- scratch (static device globals; no allocation) ----------
__device__ float g_h[H];
__device__ float g_heff[H];
__device__ float g_ksum[H];
__device__ float g_t1[FF];
__device__ float g_t2[FF];
__device__ float g_traj[NSEG][H];
__device__ float g_gi0[(size_t)T * SEQ * G3];   // precomputed x@wi0^T + bi0
__device__ float g_h1[2][R * H];                // ping-pong layer-1 hidden
__device__ float g_h2[2][R * H];                // ping-pong layer-2 hidden

__device__ __forceinline__ float sigf(float v) { return 1.f / (1.f + expf(-v)); }

// ---------------- ODE: zero init ------------------------------------------
__global__ void zero_h() { g_h[threadIdx.x] = 0.f; }   // <<<1,1024>>>

// ---------------- ODE: fused GEMV stages -----------------------------------
// stage 1: t1 = tanh(W1 @ v + b1), v = (mode==0 ? h : heff)
// stage 2: t2 = tanh(W2 @ t1 + b2)
// stage 3: k  = W3 @ t2 + b3, RK4 combine fused in epilogue
__global__ void ode_gemv(const float* __restrict__ W, const float* __restrict__ bias,
                         int K, int stage, int mode, int traj_idx) {
    __shared__ __align__(16) float sv[FF];
    const float* v = (stage == 1) ? (mode == 0 ? g_h : g_heff)
                                  : (stage == 2 ? g_t1 : g_t2);
    for (int i = threadIdx.x; i < K; i += blockDim.x) sv[i] = v[i];
    __syncthreads();

    int warp = threadIdx.x >> 5, lane = threadIdx.x & 31;
    int row  = (blockIdx.x << 3) + warp;   // 8 rows per block
    const float* wr = W + (size_t)row * K;
    float s = 0.f;
    for (int k = lane * 4; k < K; k += 128) {
        float4 wv = *(const float4*)(wr + k);
        float4 vv = *(const float4*)(sv + k);
        s += wv.x * vv.x + wv.y * vv.y + wv.z * vv.z + wv.w * vv.w;
    }
#pragma unroll
    for (int o = 16; o; o >>= 1) s += __shfl_xor_sync(0xffffffffu, s, o);

    if (lane == 0) {
        s += bias[row];
        if (stage == 1)      g_t1[row] = tanhf(s);
        else if (stage == 2) g_t2[row] = tanhf(s);
        else {
            float kv = s;
            if (mode == 0)      { g_ksum[row] = kv;           g_heff[row] = g_h[row] + 0.5f * DT * kv; }
            else if (mode == 1) { g_ksum[row] += 2.f * kv;    g_heff[row] = g_h[row] + 0.5f * DT * kv; }
            else if (mode == 2) { g_ksum[row] += 2.f * kv;    g_heff[row] = g_h[row] + DT * kv; }
            else {
                float hn = g_h[row] + (DT / 6.f) * (g_ksum[row] + kv);
                g_h[row] = hn;
                if (traj_idx >= 0) g_traj[traj_idx][row] = hn;
            }
        }
    }
}

// ---------------- gi0 precompute: (T*SEQ) x G3 = x @ wi0^T + bi0 -----------
// grid (T, G3/64), block 256 (16x16), thread tile 4x4, K-chunk 16
__global__ void gi0_gemm(const float* __restrict__ x, const float* __restrict__ wi0,
                         const float* __restrict__ bi0) {
    __shared__ __align__(16) float As[16][68];
    __shared__ __align__(16) float Ws[16][68];
    int t = blockIdx.x, n0 = blockIdx.y * 64;
    int tid = threadIdx.x, tx = tid & 15, ty = tid >> 4;
    float acc[4][4] = {};

    for (int k0 = 0; k0 < H; k0 += 16) {
#pragma unroll
        for (int j = 0; j < 4; j++) {
            int e = tid + j * 256;
            int kc = e & 15, row = e >> 4;
            As[kc][row] = x[((size_t)row * T + t) * H + k0 + kc];           // x[b][t][k]
            Ws[kc][row] = wi0[(size_t)(n0 + row) * H + k0 + kc];
        }
        __syncthreads();
#pragma unroll
        for (int kk = 0; kk < 16; kk++) {
            float4 a = *(const float4*)(&As[kk][ty * 4]);
            float4 w = *(const float4*)(&Ws[kk][tx * 4]);
            float av[4] = {a.x, a.y, a.z, a.w};
            float wv[4] = {w.x, w.y, w.z, w.w};
#pragma unroll
            for (int i = 0; i < 4; i++)
#pragma unroll
                for (int j = 0; j < 4; j++) acc[i][j] += av[i] * wv[j];
        }
        __syncthreads();
    }
#pragma unroll
    for (int i = 0; i < 4; i++) {
        int b = ty * 4 + i;
        size_t base = ((size_t)t * SEQ + b) * G3 + n0;
#pragma unroll
        for (int j = 0; j < 4; j++) {
            int c = tx * 4 + j;
            g_gi0[base + c] = acc[i][j] + bi0[n0 + c];
        }
    }
}

// ---------------- init h1/h2 from trajectory -------------------------------
__global__ void init_states() {      // <<<R, H>>>
    int r = blockIdx.x, j = threadIdx.x;
    float v = g_traj[r & 7][j];      // run r = t*8 + i  ->  init = traj[i]
    g_h1[0][(size_t)r * H + j] = v;
    g_h2[0][(size_t)r * H + j] = v;
}

// ---------------- GRU layer 0 step: gh0 GEMM + fused cell update -----------
// grid (4, 32): BM=64 runs x BN=32 hidden cols (x3 gates). block 256 (16x16)
__global__ void gru_l0(const float* __restrict__ wh0, const float* __restrict__ bh0,
                       int step, int src) {
    __shared__ float As[32][65];
    __shared__ float Ws[32][97];
    int r0 = blockIdx.x * 64, n0 = blockIdx.y * 32;
    int tid = threadIdx.x, tx = tid & 15, ty = tid >> 4;
    const float* h1s = g_h1[src];
    float acc[3][4][2] = {};

    for (int k0 = 0; k0 < H; k0 += 32) {
#pragma unroll
        for (int j = 0; j < 8; j++) {              // A tile: 64 x 32
            int e = tid + j * 256;
            int kc = e & 31, row = e >> 5;
            int r = r0 + row;
            As[kc][row] = (r < R) ? h1s[(size_t)r * H + k0 + kc] : 0.f;
        }
#pragma unroll
        for (int j = 0; j < 12; j++) {             // W tile: 96 x 32 (3 gates)
            int e = tid + j * 256;
            int kc = e & 31, wr = e >> 5;
            int gate = wr >> 5, c = wr & 31;
            Ws[kc][wr] = wh0[(size_t)(gate * H + n0 + c) * H + k0 + kc];
        }
        __syncthreads();
#pragma unroll
        for (int kk = 0; kk < 32; kk++) {
            float a[4], w[3][2];
#pragma unroll
            for (int u = 0; u < 4; u++) a[u] = As[kk][ty + 16 * u];
#pragma unroll
            for (int g = 0; g < 3; g++) {
                w[g][0] = Ws[kk][g * 32 + tx];
                w[g][1] = Ws[kk][g * 32 + tx + 16];
            }
#pragma unroll
            for (int g = 0; g < 3; g++)
#pragma unroll
                for (int u = 0; u < 4; u++)
#pragma unroll
                    for (int v = 0; v < 2; v++) acc[g][u][v] += a[u] * w[g][v];
        }
        __syncthreads();
    }

    float* h1d = g_h1[src ^ 1];
#pragma unroll
    for (int u = 0; u < 4; u++) {
        int r = r0 + ty + 16 * u;
        if (r >= R) continue;
        int t = r >> 3;
        const float* gi = g_gi0 + ((size_t)(t * SEQ + step)) * G3;
#pragma unroll
        for (int v = 0; v < 2; v++) {
            int j = n0 + tx + 16 * v;
            float ghr = acc[0][u][v] + bh0[j];
            float ghz = acc[1][u][v] + bh0[H + j];
            float ghn = acc[2][u][v] + bh0[2 * H + j];
            float rg = sigf(gi[j] + ghr);
            float z  = sigf(gi[H + j] + ghz);
            float n  = tanhf(gi[2 * H + j] + rg * ghn);
            float hp = h1s[(size_t)r * H + j];
            h1d[(size_t)r * H + j] = (1.f - z) * n + z * hp;
        }
    }
}

// ---------------- GRU layer 1 step: gi1 + gh1 GEMMs + fused update + out ---
__global__ void gru_l1(const float* __restrict__ wi1, const float* __restrict__ bi1,
                       const float* __restrict__ wh1, const float* __restrict__ bh1,
                       float* __restrict__ out, int step, int src) {
    __shared__ float A1[32][65];
    __shared__ float A2[32][65];
    __shared__ float W1[32][97];
    __shared__ float W2[32][97];
    int r0 = blockIdx.x * 64, n0 = blockIdx.y * 32;
    int tid = threadIdx.x, tx = tid & 15, ty = tid >> 4;
    const float* h1n = g_h1[src ^ 1];   // new h1 from gru_l0 this step
    const float* h2s = g_h2[src];
    float accI[3][4][2] = {};
    float accH[3][4][2] = {};

    for (int k0 = 0; k0 < H; k0 += 32) {
#pragma unroll
        for (int j = 0; j < 8; j++) {
            int e = tid + j * 256;
            int kc = e & 31, row = e >> 5;
            int r = r0 + row;
            A1[kc][row] = (r < R) ? h1n[(size_t)r * H + k0 + kc] : 0.f;
            A2[kc][row] = (r < R) ? h2s[(size_t)r * H + k0 + kc] : 0.f;
        }
#pragma unroll
        for (int j = 0; j < 12; j++) {
            int e = tid + j * 256;
            int kc = e & 31, wr = e >> 5;
            int gate = wr >> 5, c = wr & 31;
            W1[kc][wr] = wi1[(size_t)(gate * H + n0 + c) * H + k0 + kc];
            W2[kc][wr] = wh1[(size_t)(gate * H + n0 + c) * H + k0 + kc];
        }
        __syncthreads();
#pragma unroll
        for (int kk = 0; kk < 32; kk++) {
            float a1[4], a2[4], w1[3][2], w2[3][2];
#pragma unroll
            for (int u = 0; u < 4; u++) {
                a1[u] = A1[kk][ty + 16 * u];
                a2[u] = A2[kk][ty + 16 * u];
            }
#pragma unroll
            for (int g = 0; g < 3; g++) {
                w1[g][0] = W1[kk][g * 32 + tx];  w1[g][1] = W1[kk][g * 32 + tx + 16];
                w2[g][0] = W2[kk][g * 32 + tx];  w2[g][1] = W2[kk][g * 32 + tx + 16];
            }
#pragma unroll
            for (int g = 0; g < 3; g++)
#pragma unroll
                for (int u = 0; u < 4; u++)
#pragma unroll
                    for (int v = 0; v < 2; v++) {
                        accI[g][u][v] += a1[u] * w1[g][v];
                        accH[g][u][v] += a2[u] * w2[g][v];
                    }
        }
        __syncthreads();
    }

    float* h2d = g_h2[src ^ 1];
#pragma unroll
    for (int u = 0; u < 4; u++) {
        int r = r0 + ty + 16 * u;
        if (r >= R) continue;
#pragma unroll
        for (int v = 0; v < 2; v++) {
            int j = n0 + tx + 16 * v;
            float gir = accI[0][u][v] + bi1[j];
            float giz = accI[1][u][v] + bi1[H + j];
            float gin = accI[2][u][v] + bi1[2 * H + j];
            float ghr = accH[0][u][v] + bh1[j];
            float ghz = accH[1][u][v] + bh1[H + j];
            float ghn = accH[2][u][v] + bh1[2 * H + j];
            float rg = sigf(gir + ghr);
            float z  = sigf(giz + ghz);
            float n  = tanhf(gin + rg * ghn);
            float hp = h2s[(size_t)r * H + j];
            float hn = (1.f - z) * n + z * hp;
            h2d[(size_t)r * H + j] = hn;
            out[((size_t)step * R + r) * H + j] = hn;   // out[b=step][r][j]
        }
    }
}

// ---------------- launcher --------------------------------------------------
extern "C" void kernel_launch(void* const* d_in, const int* in_sizes, int n_in,
                              void* d_out, int out_size) {
    const float* x   = (const float*)d_in[0];
    const float* w1  = (const float*)d_in[1];
    const float* b1  = (const float*)d_in[2];
    const float* w2  = (const float*)d_in[3];
    const float* b2  = (const float*)d_in[4];
    const float* w3  = (const float*)d_in[5];
    const float* b3  = (const float*)d_in[6];
    const float* wi0 = (const float*)d_in[7];
    const float* wh0 = (const float*)d_in[8];
    const float* bi0 = (const float*)d_in[9];
    const float* bh0 = (const float*)d_in[10];
    const float* wi1 = (const float*)d_in[11];
    const float* wh1 = (const float*)d_in[12];
    const float* bi1 = (const float*)d_in[13];
    const float* bh1 = (const float*)d_in[14];
    float* out = (float*)d_out;

    zero_h<<<1, 1024>>>();

    // gi0 precompute (independent of ODE, ordered on same stream)
    gi0_gemm<<<dim3(T, G3 / 64), 256>>>(x, wi0, bi0);

    // ODE trajectory: 8 intervals x 4 RK4 substeps x 4 evals x 3 GEMVs
    for (int iv = 0; iv < NSEG; iv++)
        for (int sb = 0; sb < SUB; sb++)
            for (int m = 0; m < 4; m++) {
                ode_gemv<<<FF / 8, 256>>>(w1, b1, H,  1, m, -1);
                ode_gemv<<<FF / 8, 256>>>(w2, b2, FF, 2, m, -1);
                int ti = (m == 3 && sb == SUB - 1) ? iv : -1;
                ode_gemv<<<H / 8, 256>>>(w3, b3, FF, 3, m, ti);
            }

    init_states<<<R, H>>>();

    // 64 sequential GRU steps over 240 parallel runs
    for (int step = 0; step < SEQ; step++) {
        int src = step & 1;
        gru_l0<<<dim3(4, 32), 256>>>(wh0, bh0, step, src);
        gru_l1<<<dim3(4, 32), 256>>>(wi1, bi1, wh1, bh1, out, step, src);
    }
}

// round 3
// speedup vs baseline: 1.0355x; 1.0355x over previous
#include <cuda_runtime.h>
#include <cstdint>
#include <cstddef>

#define H    1024
#define FF   2048
#define G3   3072
#define SEQ  64
#define T    30
#define NSEG 8
#define SUB  4
#define R    240
#define DT   (1.0f/32.0f)
#define NB   148
#define NWARP (NB*8)

typedef unsigned long long ull;

// ---------------- scratch (static device globals; no allocation) ----------
__device__ float g_h[H], g_heff[H], g_t1[FF], g_t2[FF];
__device__ float g_traj[NSEG][H];
__device__ float g_gi0[(size_t)T * SEQ * G3];
__device__ float g_h1[2][R * H];
__device__ float g_h2[2][R * H];
__device__ unsigned g_cnt;   // barrier arrive count (self-resetting)
__device__ unsigned g_gen;   // barrier generation (monotone across replays)

__device__ __forceinline__ float sigf(float v) { return 1.f / (1.f + expf(-v)); }

// ---- packed f32x2 helpers (B300: FFMA rt=2; f32x2 doubles fp32 rate) ------
__device__ __forceinline__ ull pk2(float x) {
    ull r; asm("mov.b64 %0, {%1, %1};" : "=l"(r) : "f"(x)); return r;
}
__device__ __forceinline__ ull pk2b(float x, float y) {
    ull r; asm("mov.b64 %0, {%1, %2};" : "=l"(r) : "f"(x), "f"(y)); return r;
}
__device__ __forceinline__ void fma2(ull& d, ull a, ull b) {
    asm("fma.rn.f32x2 %0, %1, %2, %0;" : "+l"(d) : "l"(a), "l"(b));
}
__device__ __forceinline__ float2 upk(ull v) {
    float2 f; asm("mov.b64 {%0, %1}, %2;" : "=f"(f.x), "=f"(f.y) : "l"(v)); return f;
}

// =================== persistent ODE kernel =================================
__device__ __forceinline__ void gbar(unsigned base, unsigned idx) {
    __syncthreads();
    if (threadIdx.x == 0) {
        __threadfence();
        unsigned old = atomicAdd(&g_cnt, 1u);
        if (old == NB - 1) {
            g_cnt = 0u;
            __threadfence();
            atomicAdd(&g_gen, 1u);
        } else {
            while (((*(volatile unsigned*)&g_gen) - base) < idx) { }
        }
        __threadfence();
    }
    __syncthreads();
}

__device__ __forceinline__ float rowdot(const float* __restrict__ wr,
                                        const float* __restrict__ sv,
                                        int K, int lane) {
    float s = 0.f;
#pragma unroll 4
    for (int k = lane * 4; k < K; k += 128) {
        float4 w = *(const float4*)(wr + k);
        float4 v = *(const float4*)(sv + k);
        s += w.x * v.x + w.y * v.y + w.z * v.z + w.w * v.w;
    }
#pragma unroll
    for (int o = 16; o; o >>= 1) s += __shfl_xor_sync(0xffffffffu, s, o);
    return s;
}

__global__ void __launch_bounds__(256, 1) ode_all(
    const float* __restrict__ w1, const float* __restrict__ b1,
    const float* __restrict__ w2, const float* __restrict__ b2,
    const float* __restrict__ w3, const float* __restrict__ b3) {
    __shared__ __align__(16) float sv[FF];
    __shared__ unsigned sbase;
    int tid = threadIdx.x, lane = tid & 31, warp = tid >> 5;
    int wg = blockIdx.x * 8 + warp;

    if (tid == 0) sbase = *(volatile unsigned*)&g_gen;  // pre-launch gen snapshot
    if (blockIdx.x == 0)
        for (int i = tid; i < H; i += 256) __stcg(&g_h[i], 0.f);
    __syncthreads();
    unsigned base = sbase, bi = 0;
    gbar(base, ++bi);

    float hreg = 0.f, ks = 0.f;   // lane0-of-warp-wg state for row wg (wg < H)

    for (int iv = 0; iv < NSEG; iv++)
    for (int sb = 0; sb < SUB; sb++)
    for (int m = 0; m < 4; m++) {
        // stage 1: t1 = tanh(W1 @ v + b1)
        const float* vsrc = (m == 0) ? g_h : g_heff;
        for (int i = tid; i < H; i += 256) sv[i] = __ldcg(vsrc + i);
        __syncthreads();
        for (int row = wg; row < FF; row += NWARP) {
            float s = rowdot(w1 + (size_t)row * H, sv, H, lane);
            if (lane == 0) __stcg(&g_t1[row], tanhf(s + b1[row]));
        }
        gbar(base, ++bi);

        // stage 2: t2 = tanh(W2 @ t1 + b2)
        for (int i = tid; i < FF; i += 256) sv[i] = __ldcg(&g_t1[i]);
        __syncthreads();
        for (int row = wg; row < FF; row += NWARP) {
            float s = rowdot(w2 + (size_t)row * FF, sv, FF, lane);
            if (lane == 0) __stcg(&g_t2[row], tanhf(s + b2[row]));
        }
        gbar(base, ++bi);

        // stage 3: k = W3 @ t2 + b3, fused RK4 combine
        for (int i = tid; i < FF; i += 256) sv[i] = __ldcg(&g_t2[i]);
        __syncthreads();
        if (wg < H) {
            float s = rowdot(w3 + (size_t)wg * FF, sv, FF, lane);
            if (lane == 0) {
                float kv = s + b3[wg];
                if (m == 0)      { ks = kv;          __stcg(&g_heff[wg], hreg + 0.5f * DT * kv); }
                else if (m == 1) { ks += 2.f * kv;   __stcg(&g_heff[wg], hreg + 0.5f * DT * kv); }
                else if (m == 2) { ks += 2.f * kv;   __stcg(&g_heff[wg], hreg + DT * kv); }
                else {
                    hreg += (DT / 6.f) * (ks + kv);
                    __stcg(&g_h[wg], hreg);
                    if (sb == SUB - 1) g_traj[iv][wg] = hreg;
                }
            }
        }
        gbar(base, ++bi);
    }
}

// ---------------- gi0 precompute: (T*SEQ) x G3 = x @ wi0^T + bi0 -----------
__global__ void gi0_gemm(const float* __restrict__ x, const float* __restrict__ wi0,
                         const float* __restrict__ bi0) {
    __shared__ __align__(16) float As[16][68];
    __shared__ __align__(16) float Ws[16][68];
    int t = blockIdx.x, n0 = blockIdx.y * 64;
    int tid = threadIdx.x, tx = tid & 15, ty = tid >> 4;
    ull acc2[4][2] = {};

    for (int k0 = 0; k0 < H; k0 += 16) {
#pragma unroll
        for (int j = 0; j < 4; j++) {
            int e = tid + j * 256;
            int kc = e & 15, row = e >> 4;
            As[kc][row] = x[((size_t)row * T + t) * H + k0 + kc];
            Ws[kc][row] = wi0[(size_t)(n0 + row) * H + k0 + kc];
        }
        __syncthreads();
#pragma unroll
        for (int kk = 0; kk < 16; kk++) {
            float4 a = *(const float4*)(&As[kk][ty * 4]);
            float4 w = *(const float4*)(&Ws[kk][tx * 4]);
            ull w01 = pk2b(w.x, w.y), w23 = pk2b(w.z, w.w);
            float av[4] = {a.x, a.y, a.z, a.w};
#pragma unroll
            for (int i = 0; i < 4; i++) {
                ull ai = pk2(av[i]);
                fma2(acc2[i][0], ai, w01);
                fma2(acc2[i][1], ai, w23);
            }
        }
        __syncthreads();
    }
#pragma unroll
    for (int i = 0; i < 4; i++) {
        int b = ty * 4 + i;
        size_t bb = ((size_t)t * SEQ + b) * G3 + n0;
        float2 p0 = upk(acc2[i][0]), p1 = upk(acc2[i][1]);
        int c = tx * 4;
        g_gi0[bb + c]     = p0.x + bi0[n0 + c];
        g_gi0[bb + c + 1] = p0.y + bi0[n0 + c + 1];
        g_gi0[bb + c + 2] = p1.x + bi0[n0 + c + 2];
        g_gi0[bb + c + 3] = p1.y + bi0[n0 + c + 3];
    }
}

// ---------------- init h1/h2 from trajectory -------------------------------
__global__ void init_states() {
    int r = blockIdx.x, j = threadIdx.x;
    float v = g_traj[r & 7][j];
    g_h1[0][(size_t)r * H + j] = v;
    g_h2[0][(size_t)r * H + j] = v;
}

// ---------------- GRU layer 0 step ------------------------------------------
__global__ void gru_l0(const float* __restrict__ wh0, const float* __restrict__ bh0,
                       int step, int src) {
    __shared__ __align__(16) float As[32][65];
    __shared__ __align__(16) float Ws[32][98];
    int r0 = blockIdx.x * 64, n0 = blockIdx.y * 32;
    int tid = threadIdx.x, tx = tid & 15, ty = tid >> 4;
    const float* h1s = g_h1[src];
    ull acc2[3][4] = {};

    for (int k0 = 0; k0 < H; k0 += 32) {
#pragma unroll
        for (int j = 0; j < 8; j++) {
            int e = tid + j * 256;
            int kc = e & 31, row = e >> 5;
            int r = r0 + row;
            As[kc][row] = (r < R) ? h1s[(size_t)r * H + k0 + kc] : 0.f;
        }
#pragma unroll
        for (int j = 0; j < 12; j++) {
            int e = tid + j * 256;
            int kc = e & 31, wr = e >> 5;
            int gate = wr >> 5, c = wr & 31;
            Ws[kc][wr] = wh0[(size_t)(gate * H + n0 + c) * H + k0 + kc];
        }
        __syncthreads();
#pragma unroll
        for (int kk = 0; kk < 32; kk++) {
            ull w0 = *(const ull*)&Ws[kk][2 * tx];
            ull w1v = *(const ull*)&Ws[kk][32 + 2 * tx];
            ull w2v = *(const ull*)&Ws[kk][64 + 2 * tx];
#pragma unroll
            for (int u = 0; u < 4; u++) {
                ull ap = pk2(As[kk][ty + 16 * u]);
                fma2(acc2[0][u], ap, w0);
                fma2(acc2[1][u], ap, w1v);
                fma2(acc2[2][u], ap, w2v);
            }
        }
        __syncthreads();
    }

    float* h1d = g_h1[src ^ 1];
#pragma unroll
    for (int u = 0; u < 4; u++) {
        int r = r0 + ty + 16 * u;
        if (r >= R) continue;
        const float* gi = g_gi0 + ((size_t)((r >> 3) * SEQ + step)) * G3;
        float2 pr = upk(acc2[0][u]), pz = upk(acc2[1][u]), pn = upk(acc2[2][u]);
        float gr[2] = {pr.x, pr.y}, gz[2] = {pz.x, pz.y}, gn[2] = {pn.x, pn.y};
#pragma unroll
        for (int v = 0; v < 2; v++) {
            int j = n0 + 2 * tx + v;
            float rg = sigf(gi[j] + gr[v] + bh0[j]);
            float z  = sigf(gi[H + j] + gz[v] + bh0[H + j]);
            float n  = tanhf(gi[2 * H + j] + rg * (gn[v] + bh0[2 * H + j]));
            float hp = h1s[(size_t)r * H + j];
            h1d[(size_t)r * H + j] = (1.f - z) * n + z * hp;
        }
    }
}

// ---------------- GRU layer 1 step ------------------------------------------
__global__ void gru_l1(const float* __restrict__ wi1, const float* __restrict__ bi1,
                       const float* __restrict__ wh1, const float* __restrict__ bh1,
                       float* __restrict__ out, int step, int src) {
    __shared__ __align__(16) float A1[32][65];
    __shared__ __align__(16) float A2[32][65];
    __shared__ __align__(16) float W1s[32][98];
    __shared__ __align__(16) float W2s[32][98];
    int r0 = blockIdx.x * 64, n0 = blockIdx.y * 32;
    int tid = threadIdx.x, tx = tid & 15, ty = tid >> 4;
    const float* h1n = g_h1[src ^ 1];
    const float* h2s = g_h2[src];
    ull accI2[3][4] = {};
    ull accH2[3][4] = {};

    for (int k0 = 0; k0 < H; k0 += 32) {
#pragma unroll
        for (int j = 0; j < 8; j++) {
            int e = tid + j * 256;
            int kc = e & 31, row = e >> 5;
            int r = r0 + row;
            A1[kc][row] = (r < R) ? h1n[(size_t)r * H + k0 + kc] : 0.f;
            A2[kc][row] = (r < R) ? h2s[(size_t)r * H + k0 + kc] : 0.f;
        }
#pragma unroll
        for (int j = 0; j < 12; j++) {
            int e = tid + j * 256;
            int kc = e & 31, wr = e >> 5;
            int gate = wr >> 5, c = wr & 31;
            W1s[kc][wr] = wi1[(size_t)(gate * H + n0 + c) * H + k0 + kc];
            W2s[kc][wr] = wh1[(size_t)(gate * H + n0 + c) * H + k0 + kc];
        }
        __syncthreads();
#pragma unroll
        for (int kk = 0; kk < 32; kk++) {
            ull wa0 = *(const ull*)&W1s[kk][2 * tx];
            ull wa1 = *(const ull*)&W1s[kk][32 + 2 * tx];
            ull wa2 = *(const ull*)&W1s[kk][64 + 2 * tx];
            ull wb0 = *(const ull*)&W2s[kk][2 * tx];
            ull wb1 = *(const ull*)&W2s[kk][32 + 2 * tx];
            ull wb2 = *(const ull*)&W2s[kk][64 + 2 * tx];
#pragma unroll
            for (int u = 0; u < 4; u++) {
                ull a1p = pk2(A1[kk][ty + 16 * u]);
                ull a2p = pk2(A2[kk][ty + 16 * u]);
                fma2(accI2[0][u], a1p, wa0);
                fma2(accI2[1][u], a1p, wa1);
                fma2(accI2[2][u], a1p, wa2);
                fma2(accH2[0][u], a2p, wb0);
                fma2(accH2[1][u], a2p, wb1);
                fma2(accH2[2][u], a2p, wb2);
            }
        }
        __syncthreads();
    }

    float* h2d = g_h2[src ^ 1];
#pragma unroll
    for (int u = 0; u < 4; u++) {
        int r = r0 + ty + 16 * u;
        if (r >= R) continue;
        float2 ir = upk(accI2[0][u]), iz = upk(accI2[1][u]), in2 = upk(accI2[2][u]);
        float2 hr = upk(accH2[0][u]), hz = upk(accH2[1][u]), hn2 = upk(accH2[2][u]);
        float gir[2] = {ir.x, ir.y}, giz[2] = {iz.x, iz.y}, gin[2] = {in2.x, in2.y};
        float ghr[2] = {hr.x, hr.y}, ghz[2] = {hz.x, hz.y}, ghn[2] = {hn2.x, hn2.y};
#pragma unroll
        for (int v = 0; v < 2; v++) {
            int j = n0 + 2 * tx + v;
            float rg = sigf(gir[v] + bi1[j] + ghr[v] + bh1[j]);
            float z  = sigf(giz[v] + bi1[H + j] + ghz[v] + bh1[H + j]);
            float n  = tanhf(gin[v] + bi1[2 * H + j] + rg * (ghn[v] + bh1[2 * H + j]));
            float hp = h2s[(size_t)r * H + j];
            float hn = (1.f - z) * n + z * hp;
            h2d[(size_t)r * H + j] = hn;
            out[((size_t)step * R + r) * H + j] = hn;
        }
    }
}

// ---------------- launcher --------------------------------------------------
extern "C" void kernel_launch(void* const* d_in, const int* in_sizes, int n_in,
                              void* d_out, int out_size) {
    const float* x   = (const float*)d_in[0];
    const float* w1  = (const float*)d_in[1];
    const float* b1  = (const float*)d_in[2];
    const float* w2  = (const float*)d_in[3];
    const float* b2  = (const float*)d_in[4];
    const float* w3  = (const float*)d_in[5];
    const float* b3  = (const float*)d_in[6];
    const float* wi0 = (const float*)d_in[7];
    const float* wh0 = (const float*)d_in[8];
    const float* bi0 = (const float*)d_in[9];
    const float* bh0 = (const float*)d_in[10];
    const float* wi1 = (const float*)d_in[11];
    const float* wh1 = (const float*)d_in[12];
    const float* bi1 = (const float*)d_in[13];
    const float* bh1 = (const float*)d_in[14];
    float* out = (float*)d_out;

    gi0_gemm<<<dim3(T, G3 / 64), 256>>>(x, wi0, bi0);
    ode_all<<<NB, 256>>>(w1, b1, w2, b2, w3, b3);
    init_states<<<R, H>>>();

    for (int step = 0; step < SEQ; step++) {
        int src = step & 1;
        gru_l0<<<dim3(4, 32), 256>>>(wh0, bh0, step, src);
        gru_l1<<<dim3(4, 32), 256>>>(wi1, bi1, wh1, bh1, out, step, src);
    }
}

// round 4
// speedup vs baseline: 1.2505x; 1.2077x over previous
#include <cuda_runtime.h>
#include <cstdint>
#include <cstddef>

#define H    1024
#define FF   2048
#define G3   3072
#define SEQ  64
#define T    30
#define NSEG 8
#define SUB  4
#define R    240
#define DT   (1.0f/32.0f)
#define NB   148
#define NWARP (NB*8)
#define KS   4          // K-splits per step GEMM

typedef unsigned long long ull;

// ---------------- scratch (static device globals; no allocation) ----------
__device__ float g_h[H], g_heff[H], g_t1[FF], g_t2[FF];
__device__ float g_traj[NSEG][H];
__device__ float g_gi0[(size_t)T * SEQ * G3];
__device__ float g_h1[2][R * H];
__device__ float g_h2[2][R * H];
__device__ float g_P0[(size_t)KS * R * G3];   // gh0 partials
__device__ float g_PI[(size_t)KS * R * G3];   // gi1 partials
__device__ float g_PH[(size_t)KS * R * G3];   // gh1 partials
__device__ unsigned g_cnt;
__device__ unsigned g_gen;

__device__ __forceinline__ float sigf(float v) { return 1.f / (1.f + expf(-v)); }

// ---- packed f32x2 helpers --------------------------------------------------
__device__ __forceinline__ ull pk2(float x) {
    ull r; asm("mov.b64 %0, {%1, %1};" : "=l"(r) : "f"(x)); return r;
}
__device__ __forceinline__ void fma2(ull& d, ull a, ull b) {
    asm("fma.rn.f32x2 %0, %1, %2, %0;" : "+l"(d) : "l"(a), "l"(b));
}
__device__ __forceinline__ float2 upk(ull v) {
    float2 f; asm("mov.b64 {%0, %1}, %2;" : "=f"(f.x), "=f"(f.y) : "l"(v)); return f;
}

// =================== persistent ODE kernel (unchanged from R3) =============
__device__ __forceinline__ void gbar(unsigned base, unsigned idx) {
    __syncthreads();
    if (threadIdx.x == 0) {
        __threadfence();
        unsigned old = atomicAdd(&g_cnt, 1u);
        if (old == NB - 1) {
            g_cnt = 0u;
            __threadfence();
            atomicAdd(&g_gen, 1u);
        } else {
            while (((*(volatile unsigned*)&g_gen) - base) < idx) { }
        }
        __threadfence();
    }
    __syncthreads();
}

__device__ __forceinline__ float rowdot(const float* __restrict__ wr,
                                        const float* __restrict__ sv,
                                        int K, int lane) {
    float s = 0.f;
#pragma unroll 4
    for (int k = lane * 4; k < K; k += 128) {
        float4 w = *(const float4*)(wr + k);
        float4 v = *(const float4*)(sv + k);
        s += w.x * v.x + w.y * v.y + w.z * v.z + w.w * v.w;
    }
#pragma unroll
    for (int o = 16; o; o >>= 1) s += __shfl_xor_sync(0xffffffffu, s, o);
    return s;
}

__global__ void __launch_bounds__(256, 1) ode_all(
    const float* __restrict__ w1, const float* __restrict__ b1,
    const float* __restrict__ w2, const float* __restrict__ b2,
    const float* __restrict__ w3, const float* __restrict__ b3) {
    __shared__ __align__(16) float sv[FF];
    __shared__ unsigned sbase;
    int tid = threadIdx.x, lane = tid & 31, warp = tid >> 5;
    int wg = blockIdx.x * 8 + warp;

    if (tid == 0) sbase = *(volatile unsigned*)&g_gen;
    if (blockIdx.x == 0)
        for (int i = tid; i < H; i += 256) __stcg(&g_h[i], 0.f);
    __syncthreads();
    unsigned base = sbase, bi = 0;
    gbar(base, ++bi);

    float hreg = 0.f, ks = 0.f;

    for (int iv = 0; iv < NSEG; iv++)
    for (int sb = 0; sb < SUB; sb++)
    for (int m = 0; m < 4; m++) {
        const float* vsrc = (m == 0) ? g_h : g_heff;
        for (int i = tid; i < H; i += 256) sv[i] = __ldcg(vsrc + i);
        __syncthreads();
        for (int row = wg; row < FF; row += NWARP) {
            float s = rowdot(w1 + (size_t)row * H, sv, H, lane);
            if (lane == 0) __stcg(&g_t1[row], tanhf(s + b1[row]));
        }
        gbar(base, ++bi);

        for (int i = tid; i < FF; i += 256) sv[i] = __ldcg(&g_t1[i]);
        __syncthreads();
        for (int row = wg; row < FF; row += NWARP) {
            float s = rowdot(w2 + (size_t)row * FF, sv, FF, lane);
            if (lane == 0) __stcg(&g_t2[row], tanhf(s + b2[row]));
        }
        gbar(base, ++bi);

        for (int i = tid; i < FF; i += 256) sv[i] = __ldcg(&g_t2[i]);
        __syncthreads();
        if (wg < H) {
            float s = rowdot(w3 + (size_t)wg * FF, sv, FF, lane);
            if (lane == 0) {
                float kv = s + b3[wg];
                if (m == 0)      { ks = kv;          __stcg(&g_heff[wg], hreg + 0.5f * DT * kv); }
                else if (m == 1) { ks += 2.f * kv;   __stcg(&g_heff[wg], hreg + 0.5f * DT * kv); }
                else if (m == 2) { ks += 2.f * kv;   __stcg(&g_heff[wg], hreg + DT * kv); }
                else {
                    hreg += (DT / 6.f) * (ks + kv);
                    __stcg(&g_h[wg], hreg);
                    if (sb == SUB - 1) g_traj[iv][wg] = hreg;
                }
            }
        }
        gbar(base, ++bi);
    }
}

// ---------------- gi0 precompute --------------------------------------------
__global__ void gi0_gemm(const float* __restrict__ x, const float* __restrict__ wi0,
                         const float* __restrict__ bi0) {
    __shared__ __align__(16) float As[16][68];
    __shared__ __align__(16) float Ws[16][68];
    int t = blockIdx.x, n0 = blockIdx.y * 64;
    int tid = threadIdx.x, tx = tid & 15, ty = tid >> 4;
    ull acc2[4][2] = {};

    for (int k0 = 0; k0 < H; k0 += 16) {
#pragma unroll
        for (int j = 0; j < 4; j++) {
            int e = tid + j * 256;
            int kc = e & 15, row = e >> 4;
            As[kc][row] = x[((size_t)row * T + t) * H + k0 + kc];
            Ws[kc][row] = wi0[(size_t)(n0 + row) * H + k0 + kc];
        }
        __syncthreads();
#pragma unroll
        for (int kk = 0; kk < 16; kk++) {
            ull w01 = *(const ull*)&Ws[kk][tx * 4];
            ull w23 = *(const ull*)&Ws[kk][tx * 4 + 2];
            float4 a = *(const float4*)(&As[kk][ty * 4]);
            float av[4] = {a.x, a.y, a.z, a.w};
#pragma unroll
            for (int i = 0; i < 4; i++) {
                ull ai = pk2(av[i]);
                fma2(acc2[i][0], ai, w01);
                fma2(acc2[i][1], ai, w23);
            }
        }
        __syncthreads();
    }
#pragma unroll
    for (int i = 0; i < 4; i++) {
        int b = ty * 4 + i;
        size_t bb = ((size_t)t * SEQ + b) * G3 + n0;
        float2 p0 = upk(acc2[i][0]), p1 = upk(acc2[i][1]);
        int c = tx * 4;
        g_gi0[bb + c]     = p0.x + bi0[n0 + c];
        g_gi0[bb + c + 1] = p0.y + bi0[n0 + c + 1];
        g_gi0[bb + c + 2] = p1.x + bi0[n0 + c + 2];
        g_gi0[bb + c + 3] = p1.y + bi0[n0 + c + 3];
    }
}

// ---------------- init h1/h2 from trajectory -------------------------------
__global__ void init_states() {
    int r = blockIdx.x, j = threadIdx.x;
    float v = g_traj[r & 7][j];
    g_h1[0][(size_t)r * H + j] = v;
    g_h2[0][(size_t)r * H + j] = v;
}

// ---------------- generic step GEMM (K-split partial) -----------------------
// A[R x H] row-major; W[G3 x H] row-major (3 gate blocks of H rows).
// grid (4 rblk, 32 nblk, KS ksplit), block 256. Partial P[ks][r*G3 + g*H + n].
__global__ void __launch_bounds__(256, 4) gmm(int asel, const float* __restrict__ W,
                                              int psel) {
    __shared__ ull   As2[64][33];
    __shared__ float Ws[32][98];
    const float* A = (asel == 0) ? g_h1[0] : (asel == 1) ? g_h1[1]
                   : (asel == 2) ? g_h2[0] : g_h2[1];
    float* P = (psel == 0) ? g_P0 : (psel == 1) ? g_PI : g_PH;

    int r0 = blockIdx.x * 64, n0 = blockIdx.y * 32, kz = blockIdx.z;
    int tid = threadIdx.x, tx = tid & 15, ty = tid >> 4;
    ull acc[3][4] = {};

    for (int k0 = 0; k0 < 256; k0 += 32) {
        int kb = kz * 256 + k0;
#pragma unroll
        for (int j = 0; j < 8; j++) {
            int e = tid + j * 256;
            int kc = e & 31, row = e >> 5;
            int r = r0 + row;
            float v = (r < R) ? A[(size_t)r * H + kb + kc] : 0.f;
            As2[row][kc] = pk2(v);
        }
#pragma unroll
        for (int j = 0; j < 12; j++) {
            int e = tid + j * 256;
            int kc = e & 31, wr = e >> 5;
            int gate = wr >> 5, c = wr & 31;
            Ws[kc][wr] = W[(size_t)(gate * H + n0 + c) * H + kb + kc];
        }
        __syncthreads();
#pragma unroll
        for (int kk = 0; kk < 32; kk++) {
            ull w0 = *(const ull*)&Ws[kk][2 * tx];
            ull w1 = *(const ull*)&Ws[kk][32 + 2 * tx];
            ull w2 = *(const ull*)&Ws[kk][64 + 2 * tx];
#pragma unroll
            for (int u = 0; u < 4; u++) {
                ull ap = As2[ty + 16 * u][kk];
                fma2(acc[0][u], ap, w0);
                fma2(acc[1][u], ap, w1);
                fma2(acc[2][u], ap, w2);
            }
        }
        __syncthreads();
    }

    size_t pb = (size_t)kz * ((size_t)R * G3);
#pragma unroll
    for (int u = 0; u < 4; u++) {
        int r = r0 + ty + 16 * u;
        if (r >= R) continue;
#pragma unroll
        for (int g = 0; g < 3; g++) {
            float2 p = upk(acc[g][u]);
            *(float2*)&P[pb + (size_t)r * G3 + g * H + n0 + 2 * tx] = p;
        }
    }
}

// ---------------- layer-0 finalize: sum splits + GRU nonlinearity ----------
__global__ void l0fin(const float* __restrict__ bh0, int step, int src) {
    int idx = blockIdx.x * 256 + threadIdx.x;   // grid 960
    int r = idx >> 10, j = idx & (H - 1);
    const float* h1s = g_h1[src];
    float sr = 0.f, sz = 0.f, sn = 0.f;
    size_t base = (size_t)r * G3 + j;
#pragma unroll
    for (int ks = 0; ks < KS; ks++) {
        const float* p = g_P0 + (size_t)ks * ((size_t)R * G3) + base;
        sr += p[0]; sz += p[H]; sn += p[2 * H];
    }
    const float* gi = g_gi0 + ((size_t)((r >> 3) * SEQ + step)) * G3 + j;
    float rg = sigf(gi[0] + sr + bh0[j]);
    float z  = sigf(gi[H] + sz + bh0[H + j]);
    float n  = tanhf(gi[2 * H] + rg * (sn + bh0[2 * H + j]));
    float hp = h1s[(size_t)r * H + j];
    g_h1[src ^ 1][(size_t)r * H + j] = (1.f - z) * n + z * hp;
}

// ---------------- layer-1 finalize ------------------------------------------
__global__ void l1fin(const float* __restrict__ bi1, const float* __restrict__ bh1,
                      float* __restrict__ out, int step, int src) {
    int idx = blockIdx.x * 256 + threadIdx.x;   // grid 960
    int r = idx >> 10, j = idx & (H - 1);
    const float* h2s = g_h2[src];
    float ir = 0.f, iz = 0.f, in2 = 0.f, hr = 0.f, hz = 0.f, hn = 0.f;
    size_t base = (size_t)r * G3 + j;
#pragma unroll
    for (int ks = 0; ks < KS; ks++) {
        const float* pi = g_PI + (size_t)ks * ((size_t)R * G3) + base;
        const float* ph = g_PH + (size_t)ks * ((size_t)R * G3) + base;
        ir += pi[0]; iz += pi[H]; in2 += pi[2 * H];
        hr += ph[0]; hz += ph[H]; hn  += ph[2 * H];
    }
    float rg = sigf(ir + bi1[j] + hr + bh1[j]);
    float z  = sigf(iz + bi1[H + j] + hz + bh1[H + j]);
    float n  = tanhf(in2 + bi1[2 * H + j] + rg * (hn + bh1[2 * H + j]));
    float hp = h2s[(size_t)r * H + j];
    float hv = (1.f - z) * n + z * hp;
    g_h2[src ^ 1][(size_t)r * H + j] = hv;
    out[((size_t)step * R + r) * H + j] = hv;
}

// ---------------- launcher --------------------------------------------------
extern "C" void kernel_launch(void* const* d_in, const int* in_sizes, int n_in,
                              void* d_out, int out_size) {
    const float* x   = (const float*)d_in[0];
    const float* w1  = (const float*)d_in[1];
    const float* b1  = (const float*)d_in[2];
    const float* w2  = (const float*)d_in[3];
    const float* b2  = (const float*)d_in[4];
    const float* w3  = (const float*)d_in[5];
    const float* b3  = (const float*)d_in[6];
    const float* wi0 = (const float*)d_in[7];
    const float* wh0 = (const float*)d_in[8];
    const float* bi0 = (const float*)d_in[9];
    const float* bh0 = (const float*)d_in[10];
    const float* wi1 = (const float*)d_in[11];
    const float* wh1 = (const float*)d_in[12];
    const float* bi1 = (const float*)d_in[13];
    const float* bh1 = (const float*)d_in[14];
    float* out = (float*)d_out;

    gi0_gemm<<<dim3(T, G3 / 64), 256>>>(x, wi0, bi0);
    ode_all<<<NB, 256>>>(w1, b1, w2, b2, w3, b3);
    init_states<<<R, H>>>();

    dim3 gg(4, 32, KS);
    for (int step = 0; step < SEQ; step++) {
        int src = step & 1;
        gmm<<<gg, 256>>>(src, wh0, 0);              // gh0 = h1_prev @ wh0^T
        l0fin<<<960, 256>>>(bh0, step, src);
        gmm<<<gg, 256>>>(src ^ 1, wi1, 1);          // gi1 = h1_new @ wi1^T
        gmm<<<gg, 256>>>(2 + src, wh1, 2);          // gh1 = h2_prev @ wh1^T
        l1fin<<<960, 256>>>(bi1, bh1, out, step, src);
    }
}

// round 5
// speedup vs baseline: 1.6929x; 1.3537x over previous
#include <cuda_runtime.h>
#include <cstdint>
#include <cstddef>

#define H    1024
#define FF   2048
#define G3   3072
#define SEQ  64
#define T    30
#define NSEG 8
#define SUB  4
#define R    240
#define RP   256      // padded run count
#define DT   (1.0f/32.0f)
#define NB   148
#define NWARP (NB*8)
#define KS   4        // K-splits per step GEMM
#define KC   256      // K per split

typedef unsigned long long ull;

// ---------------- scratch (static device globals; no allocation) ----------
__device__ float g_h[H], g_heff[H], g_t1[FF], g_t2[FF];
__device__ float g_traj[NSEG][H];
__device__ float g_gi0[(size_t)T * SEQ * G3];
__device__ float g_h1[2][RP * H];
__device__ float g_h2[2][RP * H];
__device__ float g_P0[(size_t)KS * RP * G3];
__device__ float g_PI[(size_t)KS * RP * G3];
__device__ float g_PH[(size_t)KS * RP * G3];
__device__ unsigned g_cnt;
__device__ unsigned g_gen;

__device__ __forceinline__ float sigf(float v) { return 1.f / (1.f + expf(-v)); }

// ---- packed f32x2 helpers --------------------------------------------------
__device__ __forceinline__ ull pk2(float x) {
    ull r; asm("mov.b64 %0, {%1, %1};" : "=l"(r) : "f"(x)); return r;
}
__device__ __forceinline__ void fma2(ull& d, ull a, ull b) {
    asm("fma.rn.f32x2 %0, %1, %2, %0;" : "+l"(d) : "l"(a), "l"(b));
}
__device__ __forceinline__ float2 upk(ull v) {
    float2 f; asm("mov.b64 {%0, %1}, %2;" : "=f"(f.x), "=f"(f.y) : "l"(v)); return f;
}

// =================== persistent ODE kernel =================================
__device__ __forceinline__ void gbar(unsigned base, unsigned idx) {
    __syncthreads();
    if (threadIdx.x == 0) {
        __threadfence();
        unsigned old = atomicAdd(&g_cnt, 1u);
        if (old == NB - 1) {
            g_cnt = 0u;
            __threadfence();
            atomicAdd(&g_gen, 1u);
        } else {
            while (((*(volatile unsigned*)&g_gen) - base) < idx) { }
        }
        __threadfence();
    }
    __syncthreads();
}

__device__ __forceinline__ float rowdot(const float* __restrict__ wr,
                                        const float* __restrict__ sv,
                                        int K, int lane) {
    float s = 0.f;
#pragma unroll 4
    for (int k = lane * 4; k < K; k += 128) {
        float4 w = *(const float4*)(wr + k);
        float4 v = *(const float4*)(sv + k);
        s += w.x * v.x + w.y * v.y + w.z * v.z + w.w * v.w;
    }
#pragma unroll
    for (int o = 16; o; o >>= 1) s += __shfl_xor_sync(0xffffffffu, s, o);
    return s;
}

__global__ void __launch_bounds__(256, 1) ode_all(
    const float* __restrict__ w1, const float* __restrict__ b1,
    const float* __restrict__ w2, const float* __restrict__ b2,
    const float* __restrict__ w3, const float* __restrict__ b3) {
    __shared__ __align__(16) float sv[FF];
    __shared__ unsigned sbase;
    int tid = threadIdx.x, lane = tid & 31, warp = tid >> 5;
    int wg = blockIdx.x * 8 + warp;

    if (tid == 0) sbase = *(volatile unsigned*)&g_gen;
    if (blockIdx.x == 0)
        for (int i = tid; i < H; i += 256) __stcg(&g_h[i], 0.f);
    __syncthreads();
    unsigned base = sbase, bi = 0;
    gbar(base, ++bi);

    float hreg = 0.f, ks = 0.f;

    for (int iv = 0; iv < NSEG; iv++)
    for (int sb = 0; sb < SUB; sb++)
    for (int m = 0; m < 4; m++) {
        const float* vsrc = (m == 0) ? g_h : g_heff;
        for (int i = tid; i < H; i += 256) sv[i] = __ldcg(vsrc + i);
        __syncthreads();
        for (int row = wg; row < FF; row += NWARP) {
            float s = rowdot(w1 + (size_t)row * H, sv, H, lane);
            if (lane == 0) __stcg(&g_t1[row], tanhf(s + b1[row]));
        }
        gbar(base, ++bi);

        for (int i = tid; i < FF; i += 256) sv[i] = __ldcg(&g_t1[i]);
        __syncthreads();
        for (int row = wg; row < FF; row += NWARP) {
            float s = rowdot(w2 + (size_t)row * FF, sv, FF, lane);
            if (lane == 0) __stcg(&g_t2[row], tanhf(s + b2[row]));
        }
        gbar(base, ++bi);

        for (int i = tid; i < FF; i += 256) sv[i] = __ldcg(&g_t2[i]);
        __syncthreads();
        if (wg < H) {
            float s = rowdot(w3 + (size_t)wg * FF, sv, FF, lane);
            if (lane == 0) {
                float kv = s + b3[wg];
                if (m == 0)      { ks = kv;          __stcg(&g_heff[wg], hreg + 0.5f * DT * kv); }
                else if (m == 1) { ks += 2.f * kv;   __stcg(&g_heff[wg], hreg + 0.5f * DT * kv); }
                else if (m == 2) { ks += 2.f * kv;   __stcg(&g_heff[wg], hreg + DT * kv); }
                else {
                    hreg += (DT / 6.f) * (ks + kv);
                    __stcg(&g_h[wg], hreg);
                    if (sb == SUB - 1) g_traj[iv][wg] = hreg;
                }
            }
        }
        gbar(base, ++bi);
    }
}

// ---------------- gi0 precompute --------------------------------------------
__global__ void gi0_gemm(const float* __restrict__ x, const float* __restrict__ wi0,
                         const float* __restrict__ bi0) {
    __shared__ __align__(16) float As[16][68];
    __shared__ __align__(16) float Ws[16][68];
    int t = blockIdx.x, n0 = blockIdx.y * 64;
    int tid = threadIdx.x, tx = tid & 15, ty = tid >> 4;
    ull acc2[4][2] = {};

    for (int k0 = 0; k0 < H; k0 += 16) {
#pragma unroll
        for (int j = 0; j < 4; j++) {
            int e = tid + j * 256;
            int kc = e & 15, row = e >> 4;
            As[kc][row] = x[((size_t)row * T + t) * H + k0 + kc];
            Ws[kc][row] = wi0[(size_t)(n0 + row) * H + k0 + kc];
        }
        __syncthreads();
#pragma unroll
        for (int kk = 0; kk < 16; kk++) {
            ull w01 = *(const ull*)&Ws[kk][tx * 4];
            ull w23 = *(const ull*)&Ws[kk][tx * 4 + 2];
            float4 a = *(const float4*)(&As[kk][ty * 4]);
            float av[4] = {a.x, a.y, a.z, a.w};
#pragma unroll
            for (int i = 0; i < 4; i++) {
                ull ai = pk2(av[i]);
                fma2(acc2[i][0], ai, w01);
                fma2(acc2[i][1], ai, w23);
            }
        }
        __syncthreads();
    }
#pragma unroll
    for (int i = 0; i < 4; i++) {
        int b = ty * 4 + i;
        size_t bb = ((size_t)t * SEQ + b) * G3 + n0;
        float2 p0 = upk(acc2[i][0]), p1 = upk(acc2[i][1]);
        int c = tx * 4;
        g_gi0[bb + c]     = p0.x + bi0[n0 + c];
        g_gi0[bb + c + 1] = p0.y + bi0[n0 + c + 1];
        g_gi0[bb + c + 2] = p1.x + bi0[n0 + c + 2];
        g_gi0[bb + c + 3] = p1.y + bi0[n0 + c + 3];
    }
}

// ---------------- init h1/h2 (rows 240..255 zero-padded) --------------------
__global__ void init_states() {      // <<<RP, H>>>
    int r = blockIdx.x, j = threadIdx.x;
    float v = (r < R) ? g_traj[r & 7][j] : 0.f;
    g_h1[0][(size_t)r * H + j] = v;
    g_h1[1][(size_t)r * H + j] = v;   // keep pad rows zero in both buffers
    g_h2[0][(size_t)r * H + j] = v;
    g_h2[1][(size_t)r * H + j] = v;
}

// ---------------- step GEMM: BM=128, BN=32x3 gates, TM=8, TN=2/gate ---------
// grid (2, 32, KS), block 256. FFMA2-pipe-bound design:
// per thread-k: 8 LDS.32(A bcast) + 3 LDS.64(W pair) + 8 pk2 + 24 FFMA2.
__global__ void __launch_bounds__(256, 2) gmm(int asel, const float* __restrict__ W,
                                              int psel) {
    __shared__ __align__(16) float As[128][36];   // [m][kk] straight copy
    __shared__ __align__(16) float Ws[32][100];   // [kk][gate*32+n] transposed
    const float* A = (asel == 0) ? g_h1[0] : (asel == 1) ? g_h1[1]
                   : (asel == 2) ? g_h2[0] : g_h2[1];
    float* P = (psel == 0) ? g_P0 : (psel == 1) ? g_PI : g_PH;

    int r0 = blockIdx.x * 128, n0 = blockIdx.y * 32, kz = blockIdx.z;
    int tid = threadIdx.x, tx = tid & 15, ty = tid >> 4;
    ull acc[3][8] = {};

    for (int k0 = 0; k0 < KC; k0 += 32) {
        int kb = kz * KC + k0;
        // A fill: 128x32 floats = 4 float4/thread, no transpose, no conflicts
#pragma unroll
        for (int j = 0; j < 4; j++) {
            int lin = tid + j * 256;          // one float4 each
            int row = lin >> 3, kq = (lin & 7) << 2;
            float4 v = *(const float4*)(A + (size_t)(r0 + row) * H + kb + kq);
            *(float4*)&As[row][kq] = v;
        }
        // W fill: 96x32 floats transposed (k-major), 12 scalars/thread
#pragma unroll
        for (int j = 0; j < 12; j++) {
            int e = tid + j * 256;
            int kc = e & 31, wr = e >> 5;
            int gate = wr >> 5, c = wr & 31;
            Ws[kc][wr] = W[(size_t)(gate * H + n0 + c) * H + kb + kc];
        }
        __syncthreads();
#pragma unroll
        for (int kk = 0; kk < 32; kk++) {
            ull w0 = *(const ull*)&Ws[kk][2 * tx];
            ull w1 = *(const ull*)&Ws[kk][32 + 2 * tx];
            ull w2 = *(const ull*)&Ws[kk][64 + 2 * tx];
#pragma unroll
            for (int u = 0; u < 8; u++) {
                ull ap = pk2(As[ty * 8 + u][kk]);
                fma2(acc[0][u], ap, w0);
                fma2(acc[1][u], ap, w1);
                fma2(acc[2][u], ap, w2);
            }
        }
        __syncthreads();
    }

    size_t pb = (size_t)kz * ((size_t)RP * G3);
#pragma unroll
    for (int u = 0; u < 8; u++) {
        int r = r0 + ty * 8 + u;
        size_t rb = pb + (size_t)r * G3 + n0 + 2 * tx;
#pragma unroll
        for (int g = 0; g < 3; g++) {
            float2 p = upk(acc[g][u]);
            *(float2*)&P[rb + (size_t)g * H] = p;
        }
    }
}

// ---------------- layer-0 finalize ------------------------------------------
__global__ void l0fin(const float* __restrict__ bh0, int step, int src) {
    int idx = blockIdx.x * 256 + threadIdx.x;   // grid 960 -> 240x1024
    int r = idx >> 10, j = idx & (H - 1);
    const float* h1s = g_h1[src];
    float sr = 0.f, sz = 0.f, sn = 0.f;
    size_t base = (size_t)r * G3 + j;
#pragma unroll
    for (int ks = 0; ks < KS; ks++) {
        const float* p = g_P0 + (size_t)ks * ((size_t)RP * G3) + base;
        sr += p[0]; sz += p[H]; sn += p[2 * H];
    }
    const float* gi = g_gi0 + ((size_t)((r >> 3) * SEQ + step)) * G3 + j;
    float rg = sigf(gi[0] + sr + bh0[j]);
    float z  = sigf(gi[H] + sz + bh0[H + j]);
    float n  = tanhf(gi[2 * H] + rg * (sn + bh0[2 * H + j]));
    float hp = h1s[(size_t)r * H + j];
    g_h1[src ^ 1][(size_t)r * H + j] = (1.f - z) * n + z * hp;
}

// ---------------- layer-1 finalize ------------------------------------------
__global__ void l1fin(const float* __restrict__ bi1, const float* __restrict__ bh1,
                      float* __restrict__ out, int step, int src) {
    int idx = blockIdx.x * 256 + threadIdx.x;   // grid 960
    int r = idx >> 10, j = idx & (H - 1);
    const float* h2s = g_h2[src];
    float ir = 0.f, iz = 0.f, in2 = 0.f, hr = 0.f, hz = 0.f, hn = 0.f;
    size_t base = (size_t)r * G3 + j;
#pragma unroll
    for (int ks = 0; ks < KS; ks++) {
        const float* pi = g_PI + (size_t)ks * ((size_t)RP * G3) + base;
        const float* ph = g_PH + (size_t)ks * ((size_t)RP * G3) + base;
        ir += pi[0]; iz += pi[H]; in2 += pi[2 * H];
        hr += ph[0]; hz += ph[H]; hn  += ph[2 * H];
    }
    float rg = sigf(ir + bi1[j] + hr + bh1[j]);
    float z  = sigf(iz + bi1[H + j] + hz + bh1[H + j]);
    float n  = tanhf(in2 + bi1[2 * H + j] + rg * (hn + bh1[2 * H + j]));
    float hp = h2s[(size_t)r * H + j];
    float hv = (1.f - z) * n + z * hp;
    g_h2[src ^ 1][(size_t)r * H + j] = hv;
    out[((size_t)step * R + r) * H + j] = hv;
}

// ---------------- launcher --------------------------------------------------
extern "C" void kernel_launch(void* const* d_in, const int* in_sizes, int n_in,
                              void* d_out, int out_size) {
    const float* x   = (const float*)d_in[0];
    const float* w1  = (const float*)d_in[1];
    const float* b1  = (const float*)d_in[2];
    const float* w2  = (const float*)d_in[3];
    const float* b2  = (const float*)d_in[4];
    const float* w3  = (const float*)d_in[5];
    const float* b3  = (const float*)d_in[6];
    const float* wi0 = (const float*)d_in[7];
    const float* wh0 = (const float*)d_in[8];
    const float* bi0 = (const float*)d_in[9];
    const float* bh0 = (const float*)d_in[10];
    const float* wi1 = (const float*)d_in[11];
    const float* wh1 = (const float*)d_in[12];
    const float* bi1 = (const float*)d_in[13];
    const float* bh1 = (const float*)d_in[14];
    float* out = (float*)d_out;

    gi0_gemm<<<dim3(T, G3 / 64), 256>>>(x, wi0, bi0);
    ode_all<<<NB, 256>>>(w1, b1, w2, b2, w3, b3);
    init_states<<<RP, H>>>();

    dim3 gg(2, 32, KS);
    for (int step = 0; step < SEQ; step++) {
        int src = step & 1;
        gmm<<<gg, 256>>>(src, wh0, 0);              // gh0 = h1_prev @ wh0^T
        l0fin<<<960, 256>>>(bh0, step, src);
        gmm<<<gg, 256>>>(src ^ 1, wi1, 1);          // gi1 = h1_new @ wi1^T
        gmm<<<gg, 256>>>(2 + src, wh1, 2);          // gh1 = h2_prev @ wh1^T
        l1fin<<<960, 256>>>(bi1, bh1, out, step, src);
    }
}

// round 7
// speedup vs baseline: 2.6307x; 1.5540x over previous
#include <cuda_runtime.h>
#include <cuda_bf16.h>
#include <cstdint>
#include <cstddef>

#define H    1024
#define FF   2048
#define G3   3072
#define SEQ  64
#define T    30
#define NSEG 8
#define SUB  4
#define R    240
#define RP   256
#define DT   (1.0f/32.0f)
#define NB   148
#define NWARP (NB*8)
#define KS   4        // K-splits per step GEMM
#define KC   256      // K per split
#define BM   128
#define BN   128
#define SW   40       // smem row stride in bf16 (80 bytes, ldmatrix conflict-free)

typedef unsigned long long ull;

// ---------------- scratch (static device globals; no allocation) ----------
__device__ float g_h[H], g_heff[H], g_t1[FF], g_t2[FF];
__device__ float g_traj[NSEG][H];
__device__ __align__(16) float g_gi0[(size_t)T * SEQ * G3];
__device__ __align__(16) float g_h1[2][RP * H];
__device__ __align__(16) float g_h2[2][RP * H];
__device__ __align__(16) float g_P0[(size_t)KS * RP * G3];
__device__ __align__(16) float g_PI[(size_t)KS * RP * G3];
__device__ __align__(16) float g_PH[(size_t)KS * RP * G3];
__device__ __align__(16) __nv_bfloat16 g_Whi[3ull * G3 * H];
__device__ __align__(16) __nv_bfloat16 g_Wlo[3ull * G3 * H];
__device__ __align__(16) __nv_bfloat16 g_Ahi[4ull * RP * H];  // h1[0],h1[1],h2[0],h2[1]
__device__ __align__(16) __nv_bfloat16 g_Alo[4ull * RP * H];
__device__ unsigned g_cnt;
__device__ unsigned g_gen;

__device__ __forceinline__ float sigf(float v) { return 1.f / (1.f + expf(-v)); }

// ---- packed f32x2 helpers (gi0 path) ---------------------------------------
__device__ __forceinline__ ull pk2(float x) {
    ull r; asm("mov.b64 %0, {%1, %1};" : "=l"(r) : "f"(x)); return r;
}
__device__ __forceinline__ void fma2(ull& d, ull a, ull b) {
    asm("fma.rn.f32x2 %0, %1, %2, %0;" : "+l"(d) : "l"(a), "l"(b));
}
__device__ __forceinline__ float2 upk(ull v) {
    float2 f; asm("mov.b64 {%0, %1}, %2;" : "=f"(f.x), "=f"(f.y) : "l"(v)); return f;
}

// ---- mma helpers -------------------------------------------------------------
__device__ __forceinline__ uint32_t smem_u32(const void* p) {
    uint32_t a;
    asm("{ .reg .u64 t; cvta.to.shared.u64 t, %1; cvt.u32.u64 %0, t; }"
        : "=r"(a) : "l"(p));
    return a;
}
__device__ __forceinline__ void ldsm4(unsigned* r, uint32_t addr) {
    asm volatile("ldmatrix.sync.aligned.m8n8.x4.shared.b16 {%0,%1,%2,%3},[%4];"
                 : "=r"(r[0]), "=r"(r[1]), "=r"(r[2]), "=r"(r[3]) : "r"(addr));
}
__device__ __forceinline__ void mma16816(float* c, const unsigned* a,
                                         const unsigned* b) {
    asm volatile(
        "mma.sync.aligned.m16n8k16.row.col.f32.bf16.bf16.f32 "
        "{%0,%1,%2,%3},{%4,%5,%6,%7},{%8,%9},{%0,%1,%2,%3};"
        : "+f"(c[0]), "+f"(c[1]), "+f"(c[2]), "+f"(c[3])
        : "r"(a[0]), "r"(a[1]), "r"(a[2]), "r"(a[3]), "r"(b[0]), "r"(b[1]));
}

// =================== persistent ODE kernel =================================
__device__ __forceinline__ void gbar(unsigned base, unsigned idx) {
    __syncthreads();
    if (threadIdx.x == 0) {
        __threadfence();
        unsigned old = atomicAdd(&g_cnt, 1u);
        if (old == NB - 1) {
            g_cnt = 0u;
            __threadfence();
            atomicAdd(&g_gen, 1u);
        } else {
            while (((*(volatile unsigned*)&g_gen) - base) < idx) { }
        }
        __threadfence();
    }
    __syncthreads();
}

__device__ __forceinline__ float rowdot(const float* __restrict__ wr,
                                        const float* __restrict__ sv,
                                        int K, int lane) {
    float s = 0.f;
#pragma unroll 4
    for (int k = lane * 4; k < K; k += 128) {
        float4 w = *(const float4*)(wr + k);
        float4 v = *(const float4*)(sv + k);
        s += w.x * v.x + w.y * v.y + w.z * v.z + w.w * v.w;
    }
#pragma unroll
    for (int o = 16; o; o >>= 1) s += __shfl_xor_sync(0xffffffffu, s, o);
    return s;
}

__global__ void __launch_bounds__(256, 1) ode_all(
    const float* __restrict__ w1, const float* __restrict__ b1,
    const float* __restrict__ w2, const float* __restrict__ b2,
    const float* __restrict__ w3, const float* __restrict__ b3) {
    __shared__ __align__(16) float sv[FF];
    __shared__ unsigned sbase;
    int tid = threadIdx.x, lane = tid & 31, warp = tid >> 5;
    int wg = blockIdx.x * 8 + warp;

    if (tid == 0) sbase = *(volatile unsigned*)&g_gen;
    if (blockIdx.x == 0)
        for (int i = tid; i < H; i += 256) __stcg(&g_h[i], 0.f);
    __syncthreads();
    unsigned base = sbase, bi = 0;
    gbar(base, ++bi);

    float hreg = 0.f, ks = 0.f;

    for (int iv = 0; iv < NSEG; iv++)
    for (int sb = 0; sb < SUB; sb++)
    for (int m = 0; m < 4; m++) {
        const float* vsrc = (m == 0) ? g_h : g_heff;
        for (int i = tid; i < H; i += 256) sv[i] = __ldcg(vsrc + i);
        __syncthreads();
        for (int row = wg; row < FF; row += NWARP) {
            float s = rowdot(w1 + (size_t)row * H, sv, H, lane);
            if (lane == 0) __stcg(&g_t1[row], tanhf(s + b1[row]));
        }
        gbar(base, ++bi);

        for (int i = tid; i < FF; i += 256) sv[i] = __ldcg(&g_t1[i]);
        __syncthreads();
        for (int row = wg; row < FF; row += NWARP) {
            float s = rowdot(w2 + (size_t)row * FF, sv, FF, lane);
            if (lane == 0) __stcg(&g_t2[row], tanhf(s + b2[row]));
        }
        gbar(base, ++bi);

        for (int i = tid; i < FF; i += 256) sv[i] = __ldcg(&g_t2[i]);
        __syncthreads();
        if (wg < H) {
            float s = rowdot(w3 + (size_t)wg * FF, sv, FF, lane);
            if (lane == 0) {
                float kv = s + b3[wg];
                if (m == 0)      { ks = kv;          __stcg(&g_heff[wg], hreg + 0.5f * DT * kv); }
                else if (m == 1) { ks += 2.f * kv;   __stcg(&g_heff[wg], hreg + 0.5f * DT * kv); }
                else if (m == 2) { ks += 2.f * kv;   __stcg(&g_heff[wg], hreg + DT * kv); }
                else {
                    hreg += (DT / 6.f) * (ks + kv);
                    __stcg(&g_h[wg], hreg);
                    if (sb == SUB - 1) g_traj[iv][wg] = hreg;
                }
            }
        }
        gbar(base, ++bi);
    }
}

// ---------------- weight split: fp32 -> bf16 hi/lo --------------------------
__global__ void wsplit(const float* __restrict__ src, int m) {
    size_t i = (size_t)blockIdx.x * 256 + threadIdx.x;
    float a = src[i];
    __nv_bfloat16 hi = __float2bfloat16_rn(a);
    __nv_bfloat16 lo = __float2bfloat16_rn(a - __bfloat162float(hi));
    g_Whi[(size_t)m * G3 * H + i] = hi;
    g_Wlo[(size_t)m * G3 * H + i] = lo;
}

// ---------------- gi0 precompute (FFMA2 path) -------------------------------
__global__ void gi0_gemm(const float* __restrict__ x, const float* __restrict__ wi0,
                         const float* __restrict__ bi0) {
    __shared__ __align__(16) float As[16][68];
    __shared__ __align__(16) float Ws[16][68];
    int t = blockIdx.x, n0 = blockIdx.y * 64;
    int tid = threadIdx.x, tx = tid & 15, ty = tid >> 4;
    ull acc2[4][2] = {};

    for (int k0 = 0; k0 < H; k0 += 16) {
#pragma unroll
        for (int j = 0; j < 4; j++) {
            int e = tid + j * 256;
            int kc = e & 15, row = e >> 4;
            As[kc][row] = x[((size_t)row * T + t) * H + k0 + kc];
            Ws[kc][row] = wi0[(size_t)(n0 + row) * H + k0 + kc];
        }
        __syncthreads();
#pragma unroll
        for (int kk = 0; kk < 16; kk++) {
            ull w01 = *(const ull*)&Ws[kk][tx * 4];
            ull w23 = *(const ull*)&Ws[kk][tx * 4 + 2];
            float4 a = *(const float4*)(&As[kk][ty * 4]);
            float av[4] = {a.x, a.y, a.z, a.w};
#pragma unroll
            for (int i = 0; i < 4; i++) {
                ull ai = pk2(av[i]);
                fma2(acc2[i][0], ai, w01);
                fma2(acc2[i][1], ai, w23);
            }
        }
        __syncthreads();
    }
#pragma unroll
    for (int i = 0; i < 4; i++) {
        int b = ty * 4 + i;
        size_t bb = ((size_t)t * SEQ + b) * G3 + n0;
        float2 p0 = upk(acc2[i][0]), p1 = upk(acc2[i][1]);
        int c = tx * 4;
        g_gi0[bb + c]     = p0.x + bi0[n0 + c];
        g_gi0[bb + c + 1] = p0.y + bi0[n0 + c + 1];
        g_gi0[bb + c + 2] = p1.x + bi0[n0 + c + 2];
        g_gi0[bb + c + 3] = p1.y + bi0[n0 + c + 3];
    }
}

// ---------------- init h1/h2 + bf16 splits (pad rows zero) ------------------
__global__ void init_states() {      // <<<RP, H>>>
    int r = blockIdx.x, j = threadIdx.x;
    float v = (r < R) ? g_traj[r & 7][j] : 0.f;
    __nv_bfloat16 hi = __float2bfloat16_rn(v);
    __nv_bfloat16 lo = __float2bfloat16_rn(v - __bfloat162float(hi));
    size_t o = (size_t)r * H + j;
    g_h1[0][o] = v;  g_h1[1][o] = v;
    g_h2[0][o] = v;  g_h2[1][o] = v;
#pragma unroll
    for (int s = 0; s < 4; s++) {
        g_Ahi[(size_t)s * RP * H + o] = hi;
        g_Alo[(size_t)s * RP * H + o] = lo;
    }
}

// ================== HMMA bf16x3 step GEMM (K-split partials) ================
// C[RP x G3] partial = A @ W^T over K chunk KC. grid (2, 24, z); z<4 => problem
// A, z>=4 => problem B of a fused pair. 8 warps = 2(m) x 4(n), warp tile 64x32.
__global__ void __launch_bounds__(256, 2)
gmm_mma(int aselA, int wselA, int pselA, int aselB, int wselB, int pselB) {
    __shared__ __align__(16) __nv_bfloat16 sAhi[BM][SW];
    __shared__ __align__(16) __nv_bfloat16 sAlo[BM][SW];
    __shared__ __align__(16) __nv_bfloat16 sWhi[BN][SW];
    __shared__ __align__(16) __nv_bfloat16 sWlo[BN][SW];

    int tid = threadIdx.x, wid = tid >> 5, lane = tid & 31;
    int half = blockIdx.z >> 2, kz = blockIdx.z & 3;
    int asel = half ? aselB : aselA;
    int wsel = half ? wselB : wselA;
    int psel = half ? pselB : pselA;

    const __nv_bfloat16* aHi = g_Ahi + (size_t)asel * RP * H;
    const __nv_bfloat16* aLo = g_Alo + (size_t)asel * RP * H;
    const __nv_bfloat16* wHi = g_Whi + (size_t)wsel * G3 * H;
    const __nv_bfloat16* wLo = g_Wlo + (size_t)wsel * G3 * H;
    float* P = (psel == 0) ? g_P0 : (psel == 1) ? g_PI : g_PH;

    int r0 = blockIdx.x * BM, n0 = blockIdx.y * BN, kbase = kz * KC;
    int wm = (wid >> 2) * 64, wn = (wid & 3) * 32;

    uint32_t uAhi = smem_u32(&sAhi[0][0]);
    uint32_t uAlo = smem_u32(&sAlo[0][0]);
    uint32_t uWhi = smem_u32(&sWhi[0][0]);
    uint32_t uWlo = smem_u32(&sWlo[0][0]);
    // per-lane ldmatrix byte offsets
    uint32_t aoff = (uint32_t)(wm + (lane & 15)) * 80 + ((lane >> 4) << 4);
    uint32_t woff = (uint32_t)(wn + ((lane >> 4) << 3) + (lane & 7)) * 80
                  + (((lane >> 3) & 1) << 4);

    float acc[4][4][4] = {};

    for (int st = 0; st < KC / 32; st++) {
        int kg = kbase + st * 32;
#pragma unroll
        for (int j = 0; j < 2; j++) {
            int u = tid + j * 256;           // 512 uint4 groups per buffer
            int row = u >> 2, kc = (u & 3) << 3;
            size_t ga = (size_t)(r0 + row) * H + kg + kc;
            size_t gw = (size_t)(n0 + row) * H + kg + kc;
            *(uint4*)&sAhi[row][kc] = *(const uint4*)(aHi + ga);
            *(uint4*)&sAlo[row][kc] = *(const uint4*)(aLo + ga);
            *(uint4*)&sWhi[row][kc] = *(const uint4*)(wHi + gw);
            *(uint4*)&sWlo[row][kc] = *(const uint4*)(wLo + gw);
        }
        __syncthreads();
#pragma unroll
        for (int kh = 0; kh < 2; kh++) {
            unsigned ahi[4][4], alo[4][4], whi[2][4], wlo[2][4];
            uint32_t ko = (uint32_t)kh << 5;   // 16 bf16 = 32 bytes
#pragma unroll
            for (int mt = 0; mt < 4; mt++)
                ldsm4(ahi[mt], uAhi + aoff + mt * 1280 + ko);
#pragma unroll
            for (int p = 0; p < 2; p++)
                ldsm4(whi[p], uWhi + woff + p * 1280 + ko);
            // pass 1: Ahi x Whi
#pragma unroll
            for (int mt = 0; mt < 4; mt++)
#pragma unroll
                for (int nt = 0; nt < 4; nt++)
                    mma16816(acc[mt][nt], ahi[mt], &whi[nt >> 1][(nt & 1) * 2]);
            // pass 2: Ahi x Wlo
#pragma unroll
            for (int p = 0; p < 2; p++)
                ldsm4(wlo[p], uWlo + woff + p * 1280 + ko);
#pragma unroll
            for (int mt = 0; mt < 4; mt++)
#pragma unroll
                for (int nt = 0; nt < 4; nt++)
                    mma16816(acc[mt][nt], ahi[mt], &wlo[nt >> 1][(nt & 1) * 2]);
            // pass 3: Alo x Whi
#pragma unroll
            for (int mt = 0; mt < 4; mt++)
                ldsm4(alo[mt], uAlo + aoff + mt * 1280 + ko);
#pragma unroll
            for (int mt = 0; mt < 4; mt++)
#pragma unroll
                for (int nt = 0; nt < 4; nt++)
                    mma16816(acc[mt][nt], alo[mt], &whi[nt >> 1][(nt & 1) * 2]);
        }
        __syncthreads();
    }

    // epilogue: write K-split partials
    size_t pb = (size_t)kz * ((size_t)RP * G3);
#pragma unroll
    for (int mt = 0; mt < 4; mt++) {
        int row = r0 + wm + mt * 16 + (lane >> 2);
#pragma unroll
        for (int nt = 0; nt < 4; nt++) {
            int col = n0 + wn + nt * 8 + (lane & 3) * 2;
            float2 v0 = {acc[mt][nt][0], acc[mt][nt][1]};
            float2 v1 = {acc[mt][nt][2], acc[mt][nt][3]};
            *(float2*)&P[pb + (size_t)row * G3 + col] = v0;
            *(float2*)&P[pb + (size_t)(row + 8) * G3 + col] = v1;
        }
    }
}

// ---------------- layer-0 finalize (+ bf16 split of new h1) -----------------
__global__ void l0fin(const float* __restrict__ bh0, int step, int src) {
    int idx = blockIdx.x * 256 + threadIdx.x;   // grid 960 -> 240x1024
    int r = idx >> 10, j = idx & (H - 1);
    const float* h1s = g_h1[src];
    float sr = 0.f, sz = 0.f, sn = 0.f;
    size_t base = (size_t)r * G3 + j;
#pragma unroll
    for (int ks = 0; ks < KS; ks++) {
        const float* p = g_P0 + (size_t)ks * ((size_t)RP * G3) + base;
        sr += p[0]; sz += p[H]; sn += p[2 * H];
    }
    const float* gi = g_gi0 + ((size_t)((r >> 3) * SEQ + step)) * G3 + j;
    float rg = sigf(gi[0] + sr + bh0[j]);
    float z  = sigf(gi[H] + sz + bh0[H + j]);
    float n  = tanhf(gi[2 * H] + rg * (sn + bh0[2 * H + j]));
    float hp = h1s[(size_t)r * H + j];
    float hv = (1.f - z) * n + z * hp;
    size_t o = (size_t)r * H + j;
    int dst = src ^ 1;
    g_h1[dst][o] = hv;
    __nv_bfloat16 hi = __float2bfloat16_rn(hv);
    g_Ahi[(size_t)dst * RP * H + o] = hi;
    g_Alo[(size_t)dst * RP * H + o] =
        __float2bfloat16_rn(hv - __bfloat162float(hi));
}

// ---------------- layer-1 finalize (+ bf16 split of new h2) -----------------
__global__ void l1fin(const float* __restrict__ bi1, const float* __restrict__ bh1,
                      float* __restrict__ out, int step, int src) {
    int idx = blockIdx.x * 256 + threadIdx.x;   // grid 960
    int r = idx >> 10, j = idx & (H - 1);
    const float* h2s = g_h2[src];
    float ir = 0.f, iz = 0.f, in2 = 0.f, hr = 0.f, hz = 0.f, hn = 0.f;
    size_t base = (size_t)r * G3 + j;
#pragma unroll
    for (int ks = 0; ks < KS; ks++) {
        const float* pi = g_PI + (size_t)ks * ((size_t)RP * G3) + base;
        const float* ph = g_PH + (size_t)ks * ((size_t)RP * G3) + base;
        ir += pi[0]; iz += pi[H]; in2 += pi[2 * H];
        hr += ph[0]; hz += ph[H]; hn  += ph[2 * H];
    }
    float rg = sigf(ir + bi1[j] + hr + bh1[j]);
    float z  = sigf(iz + bi1[H + j] + hz + bh1[H + j]);
    float n  = tanhf(in2 + bi1[2 * H + j] + rg * (hn + bh1[2 * H + j]));
    float hp = h2s[(size_t)r * H + j];
    float hv = (1.f - z) * n + z * hp;
    size_t o = (size_t)r * H + j;
    int dst = src ^ 1;
    g_h2[dst][o] = hv;
    __nv_bfloat16 hi = __float2bfloat16_rn(hv);
    g_Ahi[(size_t)(2 + dst) * RP * H + o] = hi;
    g_Alo[(size_t)(2 + dst) * RP * H + o] =
        __float2bfloat16_rn(hv - __bfloat162float(hi));
    out[((size_t)step * R + r) * H + j] = hv;
}

// ---------------- launcher --------------------------------------------------
extern "C" void kernel_launch(void* const* d_in, const int* in_sizes, int n_in,
                              void* d_out, int out_size) {
    const float* x   = (const float*)d_in[0];
    const float* w1  = (const float*)d_in[1];
    const float* b1  = (const float*)d_in[2];
    const float* w2  = (const float*)d_in[3];
    const float* b2  = (const float*)d_in[4];
    const float* w3  = (const float*)d_in[5];
    const float* b3  = (const float*)d_in[6];
    const float* wi0 = (const float*)d_in[7];
    const float* wh0 = (const float*)d_in[8];
    const float* bi0 = (const float*)d_in[9];
    const float* bh0 = (const float*)d_in[10];
    const float* wi1 = (const float*)d_in[11];
    const float* wh1 = (const float*)d_in[12];
    const float* bi1 = (const float*)d_in[13];
    const float* bh1 = (const float*)d_in[14];
    float* out = (float*)d_out;

    int wsblk = (G3 * H) / 256;
    wsplit<<<wsblk, 256>>>(wh0, 0);
    wsplit<<<wsblk, 256>>>(wi1, 1);
    wsplit<<<wsblk, 256>>>(wh1, 2);

    gi0_gemm<<<dim3(T, G3 / 64), 256>>>(x, wi0, bi0);
    ode_all<<<NB, 256>>>(w1, b1, w2, b2, w3, b3);
    init_states<<<RP, H>>>();

    dim3 g1(RP / BM, G3 / BN, KS);       // single problem (gh0)
    dim3 g2(RP / BM, G3 / BN, 2 * KS);   // fused pair (gi1 + gh1)
    for (int step = 0; step < SEQ; step++) {
        int src = step & 1;
        gmm_mma<<<g1, 256>>>(src, 0, 0, src, 0, 0);           // gh0
        l0fin<<<960, 256>>>(bh0, step, src);
        gmm_mma<<<g2, 256>>>(src ^ 1, 1, 1, 2 + src, 2, 2);   // gi1 | gh1
        l1fin<<<960, 256>>>(bi1, bh1, out, step, src);
    }
}

// round 8
// speedup vs baseline: 2.8877x; 1.0977x over previous
#include <cuda_runtime.h>
#include <cuda_bf16.h>
#include <cstdint>
#include <cstddef>

#define H    1024
#define FF   2048
#define G3   3072
#define SEQ  64
#define T    30
#define NSEG 8
#define SUB  4
#define R    240
#define RP   256
#define DT   (1.0f/32.0f)
#define NB   148
#define NWARP (NB*8)
#define KS   2        // K-splits per step GEMM
#define KC   512      // K per split
#define BM   128
#define BN   128
#define MX   (T*SEQ)  // 1920 rows for gi0

// dynamic smem layout per buffer set: Ahi | Alo | Whi | Wlo, each 128 rows x 80B
#define TB   10240            // one tile buffer (128*80)
#define SETB (4*TB)           // 40960 per set
#define DSM  (2*SETB)         // 81920 total

typedef unsigned long long ull;

// ---------------- scratch (static device globals; no allocation) ----------
__device__ float g_h[H], g_heff[H], g_t1[FF], g_t2[FF];
__device__ float g_traj[NSEG][H];
__device__ __align__(16) float g_gi0[(size_t)MX * G3];
__device__ __align__(16) float g_h1[2][RP * H];
__device__ __align__(16) float g_h2[2][RP * H];
__device__ __align__(16) float g_P0[(size_t)KS * RP * G3];
__device__ __align__(16) float g_PI[(size_t)KS * RP * G3];
__device__ __align__(16) float g_PH[(size_t)KS * RP * G3];
__device__ __align__(16) __nv_bfloat16 g_Whi[4ull * G3 * H];
__device__ __align__(16) __nv_bfloat16 g_Wlo[4ull * G3 * H];
__device__ __align__(16) __nv_bfloat16 g_Ahi[4ull * RP * H];
__device__ __align__(16) __nv_bfloat16 g_Alo[4ull * RP * H];
__device__ __align__(16) __nv_bfloat16 g_Xhi[(size_t)MX * H];
__device__ __align__(16) __nv_bfloat16 g_Xlo[(size_t)MX * H];
__device__ unsigned g_cnt;
__device__ unsigned g_gen;

__device__ __forceinline__ float sigf(float v) { return 1.f / (1.f + expf(-v)); }

// ---- mma / async helpers ----------------------------------------------------
__device__ __forceinline__ uint32_t smem_u32(const void* p) {
    uint32_t a;
    asm("{ .reg .u64 t; cvta.to.shared.u64 t, %1; cvt.u32.u64 %0, t; }"
        : "=r"(a) : "l"(p));
    return a;
}
__device__ __forceinline__ void ldsm4(unsigned* r, uint32_t addr) {
    asm volatile("ldmatrix.sync.aligned.m8n8.x4.shared.b16 {%0,%1,%2,%3},[%4];"
                 : "=r"(r[0]), "=r"(r[1]), "=r"(r[2]), "=r"(r[3]) : "r"(addr));
}
__device__ __forceinline__ void mma16816(float* c, const unsigned* a,
                                         const unsigned* b) {
    asm volatile(
        "mma.sync.aligned.m16n8k16.row.col.f32.bf16.bf16.f32 "
        "{%0,%1,%2,%3},{%4,%5,%6,%7},{%8,%9},{%0,%1,%2,%3};"
        : "+f"(c[0]), "+f"(c[1]), "+f"(c[2]), "+f"(c[3])
        : "r"(a[0]), "r"(a[1]), "r"(a[2]), "r"(a[3]), "r"(b[0]), "r"(b[1]));
}
__device__ __forceinline__ void cp16(uint32_t dst, const void* src) {
    asm volatile("cp.async.ca.shared.global [%0],[%1],16;"
                 :: "r"(dst), "l"(src));
}
#define CPCOMMIT() asm volatile("cp.async.commit_group;" ::: "memory")
#define CPWAIT1()  asm volatile("cp.async.wait_group 1;" ::: "memory")
#define CPWAIT0()  asm volatile("cp.async.wait_group 0;" ::: "memory")

// =================== persistent ODE kernel =================================
__device__ __forceinline__ void gbar(unsigned base, unsigned idx) {
    __syncthreads();
    if (threadIdx.x == 0) {
        __threadfence();
        unsigned old = atomicAdd(&g_cnt, 1u);
        if (old == NB - 1) {
            g_cnt = 0u;
            __threadfence();
            atomicAdd(&g_gen, 1u);
        } else {
            while (((*(volatile unsigned*)&g_gen) - base) < idx) { }
        }
        __threadfence();
    }
    __syncthreads();
}

__device__ __forceinline__ float rowdot(const float* __restrict__ wr,
                                        const float* __restrict__ sv,
                                        int K, int lane) {
    float s = 0.f;
#pragma unroll 4
    for (int k = lane * 4; k < K; k += 128) {
        float4 w = *(const float4*)(wr + k);
        float4 v = *(const float4*)(sv + k);
        s += w.x * v.x + w.y * v.y + w.z * v.z + w.w * v.w;
    }
#pragma unroll
    for (int o = 16; o; o >>= 1) s += __shfl_xor_sync(0xffffffffu, s, o);
    return s;
}

__global__ void __launch_bounds__(256, 1) ode_all(
    const float* __restrict__ w1, const float* __restrict__ b1,
    const float* __restrict__ w2, const float* __restrict__ b2,
    const float* __restrict__ w3, const float* __restrict__ b3) {
    __shared__ __align__(16) float sv[FF];
    __shared__ unsigned sbase;
    int tid = threadIdx.x, lane = tid & 31, warp = tid >> 5;
    int wg = blockIdx.x * 8 + warp;

    if (tid == 0) sbase = *(volatile unsigned*)&g_gen;
    if (blockIdx.x == 0)
        for (int i = tid; i < H; i += 256) __stcg(&g_h[i], 0.f);
    __syncthreads();
    unsigned base = sbase, bi = 0;
    gbar(base, ++bi);

    float hreg = 0.f, ks = 0.f;

    for (int iv = 0; iv < NSEG; iv++)
    for (int sb = 0; sb < SUB; sb++)
    for (int m = 0; m < 4; m++) {
        const float* vsrc = (m == 0) ? g_h : g_heff;
        for (int i = tid; i < H; i += 256) sv[i] = __ldcg(vsrc + i);
        __syncthreads();
        for (int row = wg; row < FF; row += NWARP) {
            float s = rowdot(w1 + (size_t)row * H, sv, H, lane);
            if (lane == 0) __stcg(&g_t1[row], tanhf(s + b1[row]));
        }
        gbar(base, ++bi);

        for (int i = tid; i < FF; i += 256) sv[i] = __ldcg(&g_t1[i]);
        __syncthreads();
        for (int row = wg; row < FF; row += NWARP) {
            float s = rowdot(w2 + (size_t)row * FF, sv, FF, lane);
            if (lane == 0) __stcg(&g_t2[row], tanhf(s + b2[row]));
        }
        gbar(base, ++bi);

        for (int i = tid; i < FF; i += 256) sv[i] = __ldcg(&g_t2[i]);
        __syncthreads();
        if (wg < H) {
            float s = rowdot(w3 + (size_t)wg * FF, sv, FF, lane);
            if (lane == 0) {
                float kv = s + b3[wg];
                if (m == 0)      { ks = kv;          __stcg(&g_heff[wg], hreg + 0.5f * DT * kv); }
                else if (m == 1) { ks += 2.f * kv;   __stcg(&g_heff[wg], hreg + 0.5f * DT * kv); }
                else if (m == 2) { ks += 2.f * kv;   __stcg(&g_heff[wg], hreg + DT * kv); }
                else {
                    hreg += (DT / 6.f) * (ks + kv);
                    __stcg(&g_h[wg], hreg);
                    if (sb == SUB - 1) g_traj[iv][wg] = hreg;
                }
            }
        }
        gbar(base, ++bi);
    }
}

// ---------------- splits ------------------------------------------------------
__global__ void wsplit(const float* __restrict__ src, int m) {
    size_t i = (size_t)blockIdx.x * 256 + threadIdx.x;
    float a = src[i];
    __nv_bfloat16 hi = __float2bfloat16_rn(a);
    __nv_bfloat16 lo = __float2bfloat16_rn(a - __bfloat162float(hi));
    g_Whi[(size_t)m * G3 * H + i] = hi;
    g_Wlo[(size_t)m * G3 * H + i] = lo;
}

__global__ void xsplit(const float* __restrict__ x) {   // grid MX*H/256
    size_t i = (size_t)blockIdx.x * 256 + threadIdx.x;
    int m = (int)(i >> 10), k = (int)(i & (H - 1));
    int t = m >> 6, b = m & 63;                         // m = t*SEQ + b
    float a = x[((size_t)b * T + t) * H + k];
    __nv_bfloat16 hi = __float2bfloat16_rn(a);
    g_Xhi[i] = hi;
    g_Xlo[i] = __float2bfloat16_rn(a - __bfloat162float(hi));
}

// ---------------- init h1/h2 + bf16 splits (pad rows zero) ------------------
__global__ void init_states() {      // <<<RP, H>>>
    int r = blockIdx.x, j = threadIdx.x;
    float v = (r < R) ? g_traj[r & 7][j] : 0.f;
    __nv_bfloat16 hi = __float2bfloat16_rn(v);
    __nv_bfloat16 lo = __float2bfloat16_rn(v - __bfloat162float(hi));
    size_t o = (size_t)r * H + j;
    g_h1[0][o] = v;  g_h1[1][o] = v;
    g_h2[0][o] = v;  g_h2[1][o] = v;
#pragma unroll
    for (int s = 0; s < 4; s++) {
        g_Ahi[(size_t)s * RP * H + o] = hi;
        g_Alo[(size_t)s * RP * H + o] = lo;
    }
}

// ================== shared HMMA bf16x3 core ==================================
// computes 128x128 fp32 tile = Ahi*Whi + Ahi*Wlo + Alo*Whi over nst*32 K,
// with cp.async double-buffered tile pipeline. acc indexed [mt][nt][4].
__device__ __forceinline__ void mma_core(
    uint32_t sbase, int tid, int lane, int wm, int wn,
    const __nv_bfloat16* aHi, const __nv_bfloat16* aLo, size_t astr,
    const __nv_bfloat16* wHi, const __nv_bfloat16* wLo,
    int r0, int n0, int kbase, int nst, float acc[4][4][4]) {

    uint32_t aoff = (uint32_t)(wm + (lane & 15)) * 80 + ((lane >> 4) << 4);
    uint32_t woff = (uint32_t)(wn + ((lane >> 4) << 3) + (lane & 7)) * 80
                  + (((lane >> 3) & 1) << 4);

    // prologue: stage 0 into set 0
    {
        uint32_t sb2 = sbase;
#pragma unroll
        for (int j = 0; j < 2; j++) {
            int u = tid + j * 256;
            int row = u >> 2, kc = (u & 3) << 3;
            uint32_t doff = (uint32_t)row * 80 + ((uint32_t)kc << 1);
            size_t ga = (size_t)(r0 + row) * astr + kbase + kc;
            size_t gw = (size_t)(n0 + row) * H + kbase + kc;
            cp16(sb2 + doff,           aHi + ga);
            cp16(sb2 + TB + doff,      aLo + ga);
            cp16(sb2 + 2 * TB + doff,  wHi + gw);
            cp16(sb2 + 3 * TB + doff,  wLo + gw);
        }
        CPCOMMIT();
    }

    for (int st = 0; st < nst; st++) {
        if (st + 1 < nst) {
            int kg = kbase + (st + 1) * 32;
            uint32_t sb2 = sbase + ((st + 1) & 1) * SETB;
#pragma unroll
            for (int j = 0; j < 2; j++) {
                int u = tid + j * 256;
                int row = u >> 2, kc = (u & 3) << 3;
                uint32_t doff = (uint32_t)row * 80 + ((uint32_t)kc << 1);
                size_t ga = (size_t)(r0 + row) * astr + kg + kc;
                size_t gw = (size_t)(n0 + row) * H + kg + kc;
                cp16(sb2 + doff,           aHi + ga);
                cp16(sb2 + TB + doff,      aLo + ga);
                cp16(sb2 + 2 * TB + doff,  wHi + gw);
                cp16(sb2 + 3 * TB + doff,  wLo + gw);
            }
            CPCOMMIT();
            CPWAIT1();
        } else {
            CPWAIT0();
        }
        __syncthreads();

        uint32_t bs = sbase + (st & 1) * SETB;
        uint32_t uAhi = bs, uAlo = bs + TB, uWhi = bs + 2 * TB, uWlo = bs + 3 * TB;
#pragma unroll
        for (int kh = 0; kh < 2; kh++) {
            unsigned ahi[4][4], alo[4][4], whi[2][4], wlo[2][4];
            uint32_t ko = (uint32_t)kh << 5;
#pragma unroll
            for (int mt = 0; mt < 4; mt++)
                ldsm4(ahi[mt], uAhi + aoff + mt * 1280 + ko);
#pragma unroll
            for (int p = 0; p < 2; p++)
                ldsm4(whi[p], uWhi + woff + p * 1280 + ko);
#pragma unroll
            for (int mt = 0; mt < 4; mt++)
#pragma unroll
                for (int nt = 0; nt < 4; nt++)
                    mma16816(acc[mt][nt], ahi[mt], &whi[nt >> 1][(nt & 1) * 2]);
#pragma unroll
            for (int p = 0; p < 2; p++)
                ldsm4(wlo[p], uWlo + woff + p * 1280 + ko);
#pragma unroll
            for (int mt = 0; mt < 4; mt++)
#pragma unroll
                for (int nt = 0; nt < 4; nt++)
                    mma16816(acc[mt][nt], ahi[mt], &wlo[nt >> 1][(nt & 1) * 2]);
#pragma unroll
            for (int mt = 0; mt < 4; mt++)
                ldsm4(alo[mt], uAlo + aoff + mt * 1280 + ko);
#pragma unroll
            for (int mt = 0; mt < 4; mt++)
#pragma unroll
                for (int nt = 0; nt < 4; nt++)
                    mma16816(acc[mt][nt], alo[mt], &whi[nt >> 1][(nt & 1) * 2]);
        }
        __syncthreads();
    }
}

// ================== step GEMM (K-split partials) ============================
__global__ void __launch_bounds__(256, 2)
gmm_mma(int aselA, int wselA, int pselA, int aselB, int wselB, int pselB) {
    extern __shared__ __align__(16) char dynsm[];
    uint32_t sbase = smem_u32(dynsm);
    int tid = threadIdx.x, wid = tid >> 5, lane = tid & 31;
    int half = blockIdx.z >> 1, kz = blockIdx.z & 1;
    int asel = half ? aselB : aselA;
    int wsel = half ? wselB : wselA;
    int psel = half ? pselB : pselA;

    const __nv_bfloat16* aHi = g_Ahi + (size_t)asel * RP * H;
    const __nv_bfloat16* aLo = g_Alo + (size_t)asel * RP * H;
    const __nv_bfloat16* wHi = g_Whi + (size_t)wsel * G3 * H;
    const __nv_bfloat16* wLo = g_Wlo + (size_t)wsel * G3 * H;
    float* P = (psel == 0) ? g_P0 : (psel == 1) ? g_PI : g_PH;

    int r0 = blockIdx.x * BM, n0 = blockIdx.y * BN;
    int wm = (wid >> 2) * 64, wn = (wid & 3) * 32;

    float acc[4][4][4] = {};
    mma_core(sbase, tid, lane, wm, wn, aHi, aLo, H, wHi, wLo,
             r0, n0, kz * KC, KC / 32, acc);

    size_t pb = (size_t)kz * ((size_t)RP * G3);
#pragma unroll
    for (int mt = 0; mt < 4; mt++) {
        int row = r0 + wm + mt * 16 + (lane >> 2);
#pragma unroll
        for (int nt = 0; nt < 4; nt++) {
            int col = n0 + wn + nt * 8 + (lane & 3) * 2;
            float2 v0 = {acc[mt][nt][0], acc[mt][nt][1]};
            float2 v1 = {acc[mt][nt][2], acc[mt][nt][3]};
            *(float2*)&P[pb + (size_t)row * G3 + col] = v0;
            *(float2*)&P[pb + (size_t)(row + 8) * G3 + col] = v1;
        }
    }
}

// ================== gi0 GEMM: g_gi0 = X @ wi0^T + bi0 =======================
__global__ void __launch_bounds__(256, 2)
gi0_mma(const float* __restrict__ bi0) {
    extern __shared__ __align__(16) char dynsm[];
    uint32_t sbase = smem_u32(dynsm);
    int tid = threadIdx.x, wid = tid >> 5, lane = tid & 31;
    const __nv_bfloat16* wHi = g_Whi + 3ull * G3 * H;
    const __nv_bfloat16* wLo = g_Wlo + 3ull * G3 * H;

    int r0 = blockIdx.x * BM, n0 = blockIdx.y * BN;
    int wm = (wid >> 2) * 64, wn = (wid & 3) * 32;

    float acc[4][4][4] = {};
    mma_core(sbase, tid, lane, wm, wn, g_Xhi, g_Xlo, H, wHi, wLo,
             r0, n0, 0, H / 32, acc);

#pragma unroll
    for (int mt = 0; mt < 4; mt++) {
        int row = r0 + wm + mt * 16 + (lane >> 2);
#pragma unroll
        for (int nt = 0; nt < 4; nt++) {
            int col = n0 + wn + nt * 8 + (lane & 3) * 2;
            float b0 = bi0[col], b1 = bi0[col + 1];
            float2 v0 = {acc[mt][nt][0] + b0, acc[mt][nt][1] + b1};
            float2 v1 = {acc[mt][nt][2] + b0, acc[mt][nt][3] + b1};
            *(float2*)&g_gi0[(size_t)row * G3 + col] = v0;
            *(float2*)&g_gi0[(size_t)(row + 8) * G3 + col] = v1;
        }
    }
}

// ---------------- layer-0 finalize (+ bf16 split of new h1) -----------------
__global__ void l0fin(const float* __restrict__ bh0, int step, int src) {
    int idx = blockIdx.x * 256 + threadIdx.x;   // grid 960 -> 240x1024
    int r = idx >> 10, j = idx & (H - 1);
    const float* h1s = g_h1[src];
    float sr = 0.f, sz = 0.f, sn = 0.f;
    size_t base = (size_t)r * G3 + j;
#pragma unroll
    for (int ks = 0; ks < KS; ks++) {
        const float* p = g_P0 + (size_t)ks * ((size_t)RP * G3) + base;
        sr += p[0]; sz += p[H]; sn += p[2 * H];
    }
    const float* gi = g_gi0 + ((size_t)((r >> 3) * SEQ + step)) * G3 + j;
    float rg = sigf(gi[0] + sr + bh0[j]);
    float z  = sigf(gi[H] + sz + bh0[H + j]);
    float n  = tanhf(gi[2 * H] + rg * (sn + bh0[2 * H + j]));
    float hp = h1s[(size_t)r * H + j];
    float hv = (1.f - z) * n + z * hp;
    size_t o = (size_t)r * H + j;
    int dst = src ^ 1;
    g_h1[dst][o] = hv;
    __nv_bfloat16 hi = __float2bfloat16_rn(hv);
    g_Ahi[(size_t)dst * RP * H + o] = hi;
    g_Alo[(size_t)dst * RP * H + o] =
        __float2bfloat16_rn(hv - __bfloat162float(hi));
}

// ---------------- layer-1 finalize (+ bf16 split of new h2) -----------------
__global__ void l1fin(const float* __restrict__ bi1, const float* __restrict__ bh1,
                      float* __restrict__ out, int step, int src) {
    int idx = blockIdx.x * 256 + threadIdx.x;   // grid 960
    int r = idx >> 10, j = idx & (H - 1);
    const float* h2s = g_h2[src];
    float ir = 0.f, iz = 0.f, in2 = 0.f, hr = 0.f, hz = 0.f, hn = 0.f;
    size_t base = (size_t)r * G3 + j;
#pragma unroll
    for (int ks = 0; ks < KS; ks++) {
        const float* pi = g_PI + (size_t)ks * ((size_t)RP * G3) + base;
        const float* ph = g_PH + (size_t)ks * ((size_t)RP * G3) + base;
        ir += pi[0]; iz += pi[H]; in2 += pi[2 * H];
        hr += ph[0]; hz += ph[H]; hn  += ph[2 * H];
    }
    float rg = sigf(ir + bi1[j] + hr + bh1[j]);
    float z  = sigf(iz + bi1[H + j] + hz + bh1[H + j]);
    float n  = tanhf(in2 + bi1[2 * H + j] + rg * (hn + bh1[2 * H + j]));
    float hp = h2s[(size_t)r * H + j];
    float hv = (1.f - z) * n + z * hp;
    size_t o = (size_t)r * H + j;
    int dst = src ^ 1;
    g_h2[dst][o] = hv;
    __nv_bfloat16 hi = __float2bfloat16_rn(hv);
    g_Ahi[(size_t)(2 + dst) * RP * H + o] = hi;
    g_Alo[(size_t)(2 + dst) * RP * H + o] =
        __float2bfloat16_rn(hv - __bfloat162float(hi));
    out[((size_t)step * R + r) * H + j] = hv;
}

// ---------------- launcher --------------------------------------------------
extern "C" void kernel_launch(void* const* d_in, const int* in_sizes, int n_in,
                              void* d_out, int out_size) {
    const float* x   = (const float*)d_in[0];
    const float* w1  = (const float*)d_in[1];
    const float* b1  = (const float*)d_in[2];
    const float* w2  = (const float*)d_in[3];
    const float* b2  = (const float*)d_in[4];
    const float* w3  = (const float*)d_in[5];
    const float* b3  = (const float*)d_in[6];
    const float* wi0 = (const float*)d_in[7];
    const float* wh0 = (const float*)d_in[8];
    const float* bi0 = (const float*)d_in[9];
    const float* bh0 = (const float*)d_in[10];
    const float* wi1 = (const float*)d_in[11];
    const float* wh1 = (const float*)d_in[12];
    const float* bi1 = (const float*)d_in[13];
    const float* bh1 = (const float*)d_in[14];
    float* out = (float*)d_out;

    static int s_init = 0;
    if (!s_init) {
        cudaFuncSetAttribute(gmm_mma, cudaFuncAttributeMaxDynamicSharedMemorySize, DSM);
        cudaFuncSetAttribute(gi0_mma, cudaFuncAttributeMaxDynamicSharedMemorySize, DSM);
        s_init = 1;
    }

    int wsblk = (G3 * H) / 256;
    wsplit<<<wsblk, 256>>>(wh0, 0);
    wsplit<<<wsblk, 256>>>(wi1, 1);
    wsplit<<<wsblk, 256>>>(wh1, 2);
    wsplit<<<wsblk, 256>>>(wi0, 3);
    xsplit<<<(MX * H) / 256, 256>>>(x);

    gi0_mma<<<dim3(MX / BM, G3 / BN), 256, DSM>>>(bi0);
    ode_all<<<NB, 256>>>(w1, b1, w2, b2, w3, b3);
    init_states<<<RP, H>>>();

    dim3 g1(RP / BM, G3 / BN, KS);       // single problem (gh0)
    dim3 g2(RP / BM, G3 / BN, 2 * KS);   // fused pair (gi1 + gh1)
    for (int step = 0; step < SEQ; step++) {
        int src = step & 1;
        gmm_mma<<<g1, 256, DSM>>>(src, 0, 0, src, 0, 0);           // gh0
        l0fin<<<960, 256>>>(bh0, step, src);
        gmm_mma<<<g2, 256, DSM>>>(src ^ 1, 1, 1, 2 + src, 2, 2);   // gi1 | gh1
        l1fin<<<960, 256>>>(bi1, bh1, out, step, src);
    }
}

// round 9
// speedup vs baseline: 3.7268x; 1.2906x over previous
#include <cuda_runtime.h>
#include <cuda_bf16.h>
#include <cstdint>
#include <cstddef>

#define H    1024
#define FF   2048
#define G3   3072
#define SEQ  64
#define T    30
#define NSEG 8
#define SUB  4
#define R    240
#define RP   256
#define DT   (1.0f/32.0f)
#define NB   148
#define NWARP (NB*8)
#define KS   2        // K-splits per step GEMM problem
#define KC   512      // K per split
#define BM   128
#define BN   128
#define MX   (T*SEQ)  // 1920 rows for gi0

// dynamic smem per buffer set: Ahi | Alo | Whi | Wlo, each 128 rows x 80B
#define TB   10240
#define SETB (4*TB)
#define DSM  (2*SETB)

typedef unsigned long long ull;

// ---------------- scratch ----------------------------------------------------
__device__ float g_h[H], g_heff[H], g_t1[FF], g_t2[FF];
__device__ float g_traj[NSEG][H];
__device__ __align__(16) float g_gi0[(size_t)MX * G3];
__device__ __align__(16) float g_h1[2][RP * H];
__device__ __align__(16) float g_h2[2][RP * H];
__device__ __align__(16) float g_P0[(size_t)KS * RP * G3];
__device__ __align__(16) float g_PI[(size_t)KS * RP * G3];
__device__ __align__(16) float g_PH[(size_t)KS * RP * G3];
__device__ __align__(16) __nv_bfloat16 g_Whi[4ull * G3 * H];
__device__ __align__(16) __nv_bfloat16 g_Wlo[4ull * G3 * H];
__device__ __align__(16) __nv_bfloat16 g_Ahi[4ull * RP * H]; // h1[0],h1[1],h2[0],h2[1]
__device__ __align__(16) __nv_bfloat16 g_Alo[4ull * RP * H];
__device__ __align__(16) __nv_bfloat16 g_Xhi[(size_t)MX * H];
__device__ __align__(16) __nv_bfloat16 g_Xlo[(size_t)MX * H];
__device__ unsigned g_cnt;
__device__ unsigned g_gen;

__device__ __forceinline__ float sigf(float v) { return 1.f / (1.f + expf(-v)); }

// ---- mma / async helpers ----------------------------------------------------
__device__ __forceinline__ uint32_t smem_u32(const void* p) {
    uint32_t a;
    asm("{ .reg .u64 t; cvta.to.shared.u64 t, %1; cvt.u32.u64 %0, t; }"
        : "=r"(a) : "l"(p));
    return a;
}
__device__ __forceinline__ void ldsm4(unsigned* r, uint32_t addr) {
    asm volatile("ldmatrix.sync.aligned.m8n8.x4.shared.b16 {%0,%1,%2,%3},[%4];"
                 : "=r"(r[0]), "=r"(r[1]), "=r"(r[2]), "=r"(r[3]) : "r"(addr));
}
__device__ __forceinline__ void mma16816(float* c, const unsigned* a,
                                         const unsigned* b) {
    asm volatile(
        "mma.sync.aligned.m16n8k16.row.col.f32.bf16.bf16.f32 "
        "{%0,%1,%2,%3},{%4,%5,%6,%7},{%8,%9},{%0,%1,%2,%3};"
        : "+f"(c[0]), "+f"(c[1]), "+f"(c[2]), "+f"(c[3])
        : "r"(a[0]), "r"(a[1]), "r"(a[2]), "r"(a[3]), "r"(b[0]), "r"(b[1]));
}
__device__ __forceinline__ void cp16(uint32_t dst, const void* src) {
    asm volatile("cp.async.ca.shared.global [%0],[%1],16;" :: "r"(dst), "l"(src));
}
#define CPCOMMIT() asm volatile("cp.async.commit_group;" ::: "memory")
#define CPWAIT1()  asm volatile("cp.async.wait_group 1;" ::: "memory")
#define CPWAIT0()  asm volatile("cp.async.wait_group 0;" ::: "memory")

// =================== persistent ODE kernel =================================
__device__ __forceinline__ void gbar(unsigned base, unsigned idx) {
    __syncthreads();
    if (threadIdx.x == 0) {
        __threadfence();
        unsigned old = atomicAdd(&g_cnt, 1u);
        if (old == NB - 1) {
            g_cnt = 0u;
            __threadfence();
            atomicAdd(&g_gen, 1u);
        } else {
            while (((*(volatile unsigned*)&g_gen) - base) < idx) { }
        }
        __threadfence();
    }
    __syncthreads();
}

__device__ __forceinline__ float rowdot(const float* __restrict__ wr,
                                        const float* __restrict__ sv,
                                        int K, int lane) {
    float s = 0.f;
#pragma unroll 4
    for (int k = lane * 4; k < K; k += 128) {
        float4 w = *(const float4*)(wr + k);
        float4 v = *(const float4*)(sv + k);
        s += w.x * v.x + w.y * v.y + w.z * v.z + w.w * v.w;
    }
#pragma unroll
    for (int o = 16; o; o >>= 1) s += __shfl_xor_sync(0xffffffffu, s, o);
    return s;
}

__global__ void __launch_bounds__(256, 1) ode_all(
    const float* __restrict__ w1, const float* __restrict__ b1,
    const float* __restrict__ w2, const float* __restrict__ b2,
    const float* __restrict__ w3, const float* __restrict__ b3) {
    __shared__ __align__(16) float sv[FF];
    __shared__ unsigned sbase;
    int tid = threadIdx.x, lane = tid & 31, warp = tid >> 5;
    int wg = blockIdx.x * 8 + warp;

    if (tid == 0) sbase = *(volatile unsigned*)&g_gen;
    if (blockIdx.x == 0)
        for (int i = tid; i < H; i += 256) __stcg(&g_h[i], 0.f);
    __syncthreads();
    unsigned base = sbase, bi = 0;
    gbar(base, ++bi);

    float hreg = 0.f, ks = 0.f;

    for (int iv = 0; iv < NSEG; iv++)
    for (int sb = 0; sb < SUB; sb++)
    for (int m = 0; m < 4; m++) {
        const float* vsrc = (m == 0) ? g_h : g_heff;
        for (int i = tid; i < H; i += 256) sv[i] = __ldcg(vsrc + i);
        __syncthreads();
        for (int row = wg; row < FF; row += NWARP) {
            float s = rowdot(w1 + (size_t)row * H, sv, H, lane);
            if (lane == 0) __stcg(&g_t1[row], tanhf(s + b1[row]));
        }
        gbar(base, ++bi);

        for (int i = tid; i < FF; i += 256) sv[i] = __ldcg(&g_t1[i]);
        __syncthreads();
        for (int row = wg; row < FF; row += NWARP) {
            float s = rowdot(w2 + (size_t)row * FF, sv, FF, lane);
            if (lane == 0) __stcg(&g_t2[row], tanhf(s + b2[row]));
        }
        gbar(base, ++bi);

        for (int i = tid; i < FF; i += 256) sv[i] = __ldcg(&g_t2[i]);
        __syncthreads();
        if (wg < H) {
            float s = rowdot(w3 + (size_t)wg * FF, sv, FF, lane);
            if (lane == 0) {
                float kv = s + b3[wg];
                if (m == 0)      { ks = kv;          __stcg(&g_heff[wg], hreg + 0.5f * DT * kv); }
                else if (m == 1) { ks += 2.f * kv;   __stcg(&g_heff[wg], hreg + 0.5f * DT * kv); }
                else if (m == 2) { ks += 2.f * kv;   __stcg(&g_heff[wg], hreg + DT * kv); }
                else {
                    hreg += (DT / 6.f) * (ks + kv);
                    __stcg(&g_h[wg], hreg);
                    if (sb == SUB - 1) g_traj[iv][wg] = hreg;
                }
            }
        }
        gbar(base, ++bi);
    }
}

// ---------------- splits ------------------------------------------------------
__global__ void wsplit4(const float* __restrict__ w0, const float* __restrict__ w1,
                        const float* __restrict__ w2, const float* __restrict__ w3) {
    int m = blockIdx.y;
    const float* src = (m == 0) ? w0 : (m == 1) ? w1 : (m == 2) ? w2 : w3;
    size_t i = (size_t)blockIdx.x * 256 + threadIdx.x;
    float a = src[i];
    __nv_bfloat16 hi = __float2bfloat16_rn(a);
    g_Whi[(size_t)m * G3 * H + i] = hi;
    g_Wlo[(size_t)m * G3 * H + i] = __float2bfloat16_rn(a - __bfloat162float(hi));
}

__global__ void xsplit(const float* __restrict__ x) {
    size_t i = (size_t)blockIdx.x * 256 + threadIdx.x;
    int m = (int)(i >> 10), k = (int)(i & (H - 1));
    int t = m >> 6, b = m & 63;
    float a = x[((size_t)b * T + t) * H + k];
    __nv_bfloat16 hi = __float2bfloat16_rn(a);
    g_Xhi[i] = hi;
    g_Xlo[i] = __float2bfloat16_rn(a - __bfloat162float(hi));
}

// ---------------- init h1/h2 + bf16 splits (pad rows zero) ------------------
__global__ void init_states() {      // <<<RP, H>>>
    int r = blockIdx.x, j = threadIdx.x;
    float v = (r < R) ? g_traj[r & 7][j] : 0.f;
    __nv_bfloat16 hi = __float2bfloat16_rn(v);
    __nv_bfloat16 lo = __float2bfloat16_rn(v - __bfloat162float(hi));
    size_t o = (size_t)r * H + j;
    g_h1[0][o] = v;  g_h1[1][o] = v;
    g_h2[0][o] = v;  g_h2[1][o] = v;
#pragma unroll
    for (int s = 0; s < 4; s++) {
        g_Ahi[(size_t)s * RP * H + o] = hi;
        g_Alo[(size_t)s * RP * H + o] = lo;
    }
}

// ================== shared HMMA bf16x3 core ==================================
__device__ __forceinline__ void mma_core(
    uint32_t sbase, int tid, int lane, int wm, int wn,
    const __nv_bfloat16* aHi, const __nv_bfloat16* aLo, size_t astr,
    const __nv_bfloat16* wHi, const __nv_bfloat16* wLo,
    int r0, int n0, int kbase, int nst, float acc[4][4][4]) {

    uint32_t aoff = (uint32_t)(wm + (lane & 15)) * 80 + ((lane >> 4) << 4);
    uint32_t woff = (uint32_t)(wn + ((lane >> 4) << 3) + (lane & 7)) * 80
                  + (((lane >> 3) & 1) << 4);

    {
        uint32_t sb2 = sbase;
#pragma unroll
        for (int j = 0; j < 2; j++) {
            int u = tid + j * 256;
            int row = u >> 2, kc = (u & 3) << 3;
            uint32_t doff = (uint32_t)row * 80 + ((uint32_t)kc << 1);
            size_t ga = (size_t)(r0 + row) * astr + kbase + kc;
            size_t gw = (size_t)(n0 + row) * H + kbase + kc;
            cp16(sb2 + doff,          aHi + ga);
            cp16(sb2 + TB + doff,     aLo + ga);
            cp16(sb2 + 2 * TB + doff, wHi + gw);
            cp16(sb2 + 3 * TB + doff, wLo + gw);
        }
        CPCOMMIT();
    }

    for (int st = 0; st < nst; st++) {
        if (st + 1 < nst) {
            int kg = kbase + (st + 1) * 32;
            uint32_t sb2 = sbase + ((st + 1) & 1) * SETB;
#pragma unroll
            for (int j = 0; j < 2; j++) {
                int u = tid + j * 256;
                int row = u >> 2, kc = (u & 3) << 3;
                uint32_t doff = (uint32_t)row * 80 + ((uint32_t)kc << 1);
                size_t ga = (size_t)(r0 + row) * astr + kg + kc;
                size_t gw = (size_t)(n0 + row) * H + kg + kc;
                cp16(sb2 + doff,          aHi + ga);
                cp16(sb2 + TB + doff,     aLo + ga);
                cp16(sb2 + 2 * TB + doff, wHi + gw);
                cp16(sb2 + 3 * TB + doff, wLo + gw);
            }
            CPCOMMIT();
            CPWAIT1();
        } else {
            CPWAIT0();
        }
        __syncthreads();

        uint32_t bs = sbase + (st & 1) * SETB;
        uint32_t uAhi = bs, uAlo = bs + TB, uWhi = bs + 2 * TB, uWlo = bs + 3 * TB;
#pragma unroll
        for (int kh = 0; kh < 2; kh++) {
            unsigned ahi[4][4], alo[4][4], whi[2][4], wlo[2][4];
            uint32_t ko = (uint32_t)kh << 5;
#pragma unroll
            for (int mt = 0; mt < 4; mt++)
                ldsm4(ahi[mt], uAhi + aoff + mt * 1280 + ko);
#pragma unroll
            for (int p = 0; p < 2; p++)
                ldsm4(whi[p], uWhi + woff + p * 1280 + ko);
#pragma unroll
            for (int mt = 0; mt < 4; mt++)
#pragma unroll
                for (int nt = 0; nt < 4; nt++)
                    mma16816(acc[mt][nt], ahi[mt], &whi[nt >> 1][(nt & 1) * 2]);
#pragma unroll
            for (int p = 0; p < 2; p++)
                ldsm4(wlo[p], uWlo + woff + p * 1280 + ko);
#pragma unroll
            for (int mt = 0; mt < 4; mt++)
#pragma unroll
                for (int nt = 0; nt < 4; nt++)
                    mma16816(acc[mt][nt], ahi[mt], &wlo[nt >> 1][(nt & 1) * 2]);
#pragma unroll
            for (int mt = 0; mt < 4; mt++)
                ldsm4(alo[mt], uAlo + aoff + mt * 1280 + ko);
#pragma unroll
            for (int mt = 0; mt < 4; mt++)
#pragma unroll
                for (int nt = 0; nt < 4; nt++)
                    mma16816(acc[mt][nt], alo[mt], &whi[nt >> 1][(nt & 1) * 2]);
        }
        __syncthreads();
    }
}

__device__ __forceinline__ void mma_epi(float* P, int r0, int n0, int kz,
                                        int wm, int wn, int lane,
                                        float acc[4][4][4]) {
    size_t pb = (size_t)kz * ((size_t)RP * G3);
#pragma unroll
    for (int mt = 0; mt < 4; mt++) {
        int row = r0 + wm + mt * 16 + (lane >> 2);
#pragma unroll
        for (int nt = 0; nt < 4; nt++) {
            int col = n0 + wn + nt * 8 + (lane & 3) * 2;
            float2 v0 = {acc[mt][nt][0], acc[mt][nt][1]};
            float2 v1 = {acc[mt][nt][2], acc[mt][nt][3]};
            *(float2*)&P[pb + (size_t)row * G3 + col] = v0;
            *(float2*)&P[pb + (size_t)(row + 8) * G3 + col] = v1;
        }
    }
}

// ================== prologue GEMM: gh0(0) ====================================
__global__ void __launch_bounds__(256, 2) gmm_pro() {
    extern __shared__ __align__(16) char dynsm[];
    uint32_t sbase = smem_u32(dynsm);
    int tid = threadIdx.x, wid = tid >> 5, lane = tid & 31;
    int kz = blockIdx.z;
    int r0 = blockIdx.x * BM, n0 = blockIdx.y * BN;
    int wm = (wid >> 2) * 64, wn = (wid & 3) * 32;

    float acc[4][4][4] = {};
    mma_core(sbase, tid, lane, wm, wn, g_Ahi, g_Alo, H,          // h1 slot 0
             g_Whi, g_Wlo, r0, n0, kz * KC, KC / 32, acc);      // wh0
    mma_epi(g_P0, r0, n0, kz, wm, wn, lane, acc);
}

// ================== fused step GEMM: gi1(s), gh1(s), gh0(s+1) ================
__global__ void __launch_bounds__(256, 2) gmm3(int src) {
    extern __shared__ __align__(16) char dynsm[];
    uint32_t sbase = smem_u32(dynsm);
    int tid = threadIdx.x, wid = tid >> 5, lane = tid & 31;
    int prob = blockIdx.z >> 1, kz = blockIdx.z & 1;

    int asel = (prob == 1) ? (2 + src) : (src ^ 1);
    int wsel = (prob == 0) ? 1 : (prob == 1) ? 2 : 0;
    float* P = (prob == 0) ? g_PI : (prob == 1) ? g_PH : g_P0;

    const __nv_bfloat16* aHi = g_Ahi + (size_t)asel * RP * H;
    const __nv_bfloat16* aLo = g_Alo + (size_t)asel * RP * H;
    const __nv_bfloat16* wHi = g_Whi + (size_t)wsel * G3 * H;
    const __nv_bfloat16* wLo = g_Wlo + (size_t)wsel * G3 * H;

    int r0 = blockIdx.x * BM, n0 = blockIdx.y * BN;
    int wm = (wid >> 2) * 64, wn = (wid & 3) * 32;

    float acc[4][4][4] = {};
    mma_core(sbase, tid, lane, wm, wn, aHi, aLo, H, wHi, wLo,
             r0, n0, kz * KC, KC / 32, acc);
    mma_epi(P, r0, n0, kz, wm, wn, lane, acc);
}

// ================== gi0 GEMM =================================================
__global__ void __launch_bounds__(256, 2) gi0_mma(const float* __restrict__ bi0) {
    extern __shared__ __align__(16) char dynsm[];
    uint32_t sbase = smem_u32(dynsm);
    int tid = threadIdx.x, wid = tid >> 5, lane = tid & 31;
    const __nv_bfloat16* wHi = g_Whi + 3ull * G3 * H;
    const __nv_bfloat16* wLo = g_Wlo + 3ull * G3 * H;

    int r0 = blockIdx.x * BM, n0 = blockIdx.y * BN;
    int wm = (wid >> 2) * 64, wn = (wid & 3) * 32;

    float acc[4][4][4] = {};
    mma_core(sbase, tid, lane, wm, wn, g_Xhi, g_Xlo, H, wHi, wLo,
             r0, n0, 0, H / 32, acc);

#pragma unroll
    for (int mt = 0; mt < 4; mt++) {
        int row = r0 + wm + mt * 16 + (lane >> 2);
#pragma unroll
        for (int nt = 0; nt < 4; nt++) {
            int col = n0 + wn + nt * 8 + (lane & 3) * 2;
            float b0 = bi0[col], b1 = bi0[col + 1];
            float2 v0 = {acc[mt][nt][0] + b0, acc[mt][nt][1] + b1};
            float2 v1 = {acc[mt][nt][2] + b0, acc[mt][nt][3] + b1};
            *(float2*)&g_gi0[(size_t)row * G3 + col] = v0;
            *(float2*)&g_gi0[(size_t)(row + 8) * G3 + col] = v1;
        }
    }
}

// ---------------- vectorized finalizers --------------------------------------
__device__ __forceinline__ void ld4(float* d, const float* s) {
    float4 v = *(const float4*)s;
    d[0] = v.x; d[1] = v.y; d[2] = v.z; d[3] = v.w;
}
__device__ __forceinline__ void st_hv(int slot, size_t o, const float* hv,
                                      float* hbuf) {
    *(float4*)&hbuf[o] = make_float4(hv[0], hv[1], hv[2], hv[3]);
    __nv_bfloat16 hi[4], lo[4];
#pragma unroll
    for (int v = 0; v < 4; v++) {
        hi[v] = __float2bfloat16_rn(hv[v]);
        lo[v] = __float2bfloat16_rn(hv[v] - __bfloat162float(hi[v]));
    }
    *(uint2*)&g_Ahi[(size_t)slot * RP * H + o] = *(const uint2*)hi;
    *(uint2*)&g_Alo[(size_t)slot * RP * H + o] = *(const uint2*)lo;
}

__device__ __forceinline__ void l0fin_dev(int blk, int tid,
                                          const float* __restrict__ bh0,
                                          int step, int src) {
    int e = (blk * 256 + tid) << 2;     // element in 240*1024 space
    int r = e >> 10, j = e & 1023;
    size_t base = (size_t)r * G3 + j;
    float acc[3][4] = {};
#pragma unroll
    for (int ks = 0; ks < KS; ks++) {
        const float* p = g_P0 + (size_t)ks * ((size_t)RP * G3) + base;
#pragma unroll
        for (int g = 0; g < 3; g++) {
            float4 v = *(const float4*)(p + (size_t)g * H);
            acc[g][0] += v.x; acc[g][1] += v.y; acc[g][2] += v.z; acc[g][3] += v.w;
        }
    }
    const float* gi = g_gi0 + ((size_t)((r >> 3) * SEQ + step)) * G3 + j;
    float gr[4], gz[4], gn[4], br[4], bz[4], bn[4], hp[4], hv[4];
    ld4(gr, gi); ld4(gz, gi + H); ld4(gn, gi + 2 * H);
    ld4(br, bh0 + j); ld4(bz, bh0 + H + j); ld4(bn, bh0 + 2 * H + j);
    size_t o = (size_t)r * H + j;
    ld4(hp, &g_h1[src][o]);
#pragma unroll
    for (int v = 0; v < 4; v++) {
        float rg = sigf(gr[v] + acc[0][v] + br[v]);
        float z  = sigf(gz[v] + acc[1][v] + bz[v]);
        float n  = tanhf(gn[v] + rg * (acc[2][v] + bn[v]));
        hv[v] = (1.f - z) * n + z * hp[v];
    }
    int dst = src ^ 1;
    st_hv(dst, o, hv, g_h1[dst]);
}

__device__ __forceinline__ void l1fin_dev(int blk, int tid,
                                          const float* __restrict__ bi1,
                                          const float* __restrict__ bh1,
                                          float* __restrict__ out,
                                          int step, int src) {
    int e = (blk * 256 + tid) << 2;
    int r = e >> 10, j = e & 1023;
    size_t base = (size_t)r * G3 + j;
    float ai[3][4] = {}, ah[3][4] = {};
#pragma unroll
    for (int ks = 0; ks < KS; ks++) {
        const float* pi = g_PI + (size_t)ks * ((size_t)RP * G3) + base;
        const float* ph = g_PH + (size_t)ks * ((size_t)RP * G3) + base;
#pragma unroll
        for (int g = 0; g < 3; g++) {
            float4 vi = *(const float4*)(pi + (size_t)g * H);
            float4 vh = *(const float4*)(ph + (size_t)g * H);
            ai[g][0] += vi.x; ai[g][1] += vi.y; ai[g][2] += vi.z; ai[g][3] += vi.w;
            ah[g][0] += vh.x; ah[g][1] += vh.y; ah[g][2] += vh.z; ah[g][3] += vh.w;
        }
    }
    float bir[4], biz[4], bin[4], bhr[4], bhz[4], bhn[4], hp[4], hv[4];
    ld4(bir, bi1 + j); ld4(biz, bi1 + H + j); ld4(bin, bi1 + 2 * H + j);
    ld4(bhr, bh1 + j); ld4(bhz, bh1 + H + j); ld4(bhn, bh1 + 2 * H + j);
    size_t o = (size_t)r * H + j;
    ld4(hp, &g_h2[src][o]);
#pragma unroll
    for (int v = 0; v < 4; v++) {
        float rg = sigf(ai[0][v] + bir[v] + ah[0][v] + bhr[v]);
        float z  = sigf(ai[1][v] + biz[v] + ah[1][v] + bhz[v]);
        float n  = tanhf(ai[2][v] + bin[v] + rg * (ah[2][v] + bhn[v]));
        hv[v] = (1.f - z) * n + z * hp[v];
    }
    int dst = src ^ 1;
    st_hv(2 + dst, o, hv, g_h2[dst]);
    *(float4*)&out[((size_t)step * R + r) * H + j] =
        make_float4(hv[0], hv[1], hv[2], hv[3]);
}

__global__ void l0fin_k(const float* __restrict__ bh0, int step, int src) {
    l0fin_dev(blockIdx.x, threadIdx.x, bh0, step, src);   // <<<240,256>>>
}

// fused: blocks [0,240) -> l1fin(step); blocks [240,480) -> l0fin(step+1)
__global__ void lfin2(const float* __restrict__ bi1, const float* __restrict__ bh1,
                      const float* __restrict__ bh0, float* __restrict__ out,
                      int step, int src) {
    if (blockIdx.x < 240)
        l1fin_dev(blockIdx.x, threadIdx.x, bi1, bh1, out, step, src);
    else
        l0fin_dev(blockIdx.x - 240, threadIdx.x, bh0, step + 1, src ^ 1);
}

// ---------------- launcher --------------------------------------------------
extern "C" void kernel_launch(void* const* d_in, const int* in_sizes, int n_in,
                              void* d_out, int out_size) {
    const float* x   = (const float*)d_in[0];
    const float* w1  = (const float*)d_in[1];
    const float* b1  = (const float*)d_in[2];
    const float* w2  = (const float*)d_in[3];
    const float* b2  = (const float*)d_in[4];
    const float* w3  = (const float*)d_in[5];
    const float* b3  = (const float*)d_in[6];
    const float* wi0 = (const float*)d_in[7];
    const float* wh0 = (const float*)d_in[8];
    const float* bi0 = (const float*)d_in[9];
    const float* bh0 = (const float*)d_in[10];
    const float* wi1 = (const float*)d_in[11];
    const float* wh1 = (const float*)d_in[12];
    const float* bi1 = (const float*)d_in[13];
    const float* bh1 = (const float*)d_in[14];
    float* out = (float*)d_out;

    static int s_init = 0;
    if (!s_init) {
        cudaFuncSetAttribute(gmm_pro, cudaFuncAttributeMaxDynamicSharedMemorySize, DSM);
        cudaFuncSetAttribute(gmm3,    cudaFuncAttributeMaxDynamicSharedMemorySize, DSM);
        cudaFuncSetAttribute(gi0_mma, cudaFuncAttributeMaxDynamicSharedMemorySize, DSM);
        s_init = 1;
    }

    wsplit4<<<dim3((G3 * H) / 256, 4), 256>>>(wh0, wi1, wh1, wi0);
    xsplit<<<(MX * H) / 256, 256>>>(x);

    gi0_mma<<<dim3(MX / BM, G3 / BN), 256, DSM>>>(bi0);
    ode_all<<<NB, 256>>>(w1, b1, w2, b2, w3, b3);
    init_states<<<RP, H>>>();

    // prologue: gh0(0) from h1 slot 0, then l0fin(0)
    gmm_pro<<<dim3(RP / BM, G3 / BN, KS), 256, DSM>>>();
    l0fin_k<<<240, 256>>>(bh0, 0, 0);

    // steady state: one fused 3-problem GEMM + one fused finalize per step
    for (int s = 0; s < SEQ; s++) {
        int src = s & 1;
        int zm = (s == SEQ - 1) ? 2 * KS : 3 * KS;   // last step: no gh0(s+1)
        gmm3<<<dim3(RP / BM, G3 / BN, zm), 256, DSM>>>(src);
        int fb = (s == SEQ - 1) ? 240 : 480;         // last step: no l0fin(s+1)
        lfin2<<<fb, 256>>>(bi1, bh1, bh0, out, s, src);
    }
}